// round 4
// baseline (speedup 1.0000x reference)
#include <cuda_runtime.h>
#include <cuda_bf16.h>

#define FULL 0xffffffffu

static constexpr int B = 64;
static constexpr int S = 512;
static constexpr int H = 768;
static constexpr int L = 9;
static constexpr int CH = 128;   // chunk length for forward DP

__device__ float g_em[B * S * L];       // [b][t][j]
__device__ float g_q[B][4][9][9];       // chunk transfer rows (normal space)
__device__ float g_lac[B][4][9];        // per-row log renorm accumulators
__device__ float g_score[B];
__device__ float g_logZ[B];
__device__ float g_corr[B];

// ---------------------------------------------------------------------------
// Kernel 1: emissions = hidden @ W + b
// block 256 (8 warps). Warp = 4 row-groups x 8 lanes. Each lane: float4 x,
// W via warp-broadcast LDS.128 (1 phase). grid = 1024 (32 rows/block).
// ---------------------------------------------------------------------------
__global__ void __launch_bounds__(256) emis_kernel(const float* __restrict__ hidden,
                                                   const float* __restrict__ W,
                                                   const float* __restrict__ bias) {
    __shared__ float sWT[L * H];  // [j][h], 27648 B
    for (int i = threadIdx.x; i < L * H; i += 256) {
        int j = i / H, h = i - j * H;
        sWT[i] = W[h * L + j];
    }
    __syncthreads();

    int warp = threadIdx.x >> 5;
    int lane = threadIdx.x & 31;
    int g = lane >> 3;          // row within warp (0..3)
    int li = lane & 7;          // h-slice within row
    long row = (long)blockIdx.x * 32 + warp * 4 + g;
    const float* hr = hidden + row * H;

    float acc[9];
#pragma unroll
    for (int j = 0; j < 9; j++) acc[j] = 0.f;

#pragma unroll 4
    for (int k = 0; k < 24; k++) {
        int h = k * 32 + li * 4;
        float4 x = *(const float4*)(hr + h);
#pragma unroll
        for (int j = 0; j < 9; j++) {
            float4 w4 = *(const float4*)(sWT + j * H + h);  // broadcast across groups
            acc[j] = fmaf(x.x, w4.x, acc[j]);
            acc[j] = fmaf(x.y, w4.y, acc[j]);
            acc[j] = fmaf(x.z, w4.z, acc[j]);
            acc[j] = fmaf(x.w, w4.w, acc[j]);
        }
    }

    // reduce within each 8-lane group (3 rounds)
#pragma unroll
    for (int j = 0; j < 9; j++) {
#pragma unroll
        for (int o = 4; o > 0; o >>= 1)
            acc[j] += __shfl_xor_sync(FULL, acc[j], o);
    }

    if (li == 0) {
        float* dst = g_em + row * 9;
#pragma unroll
        for (int j = 0; j < 9; j++) dst[j] = acc[j] + bias[j];
    }
}

// ---------------------------------------------------------------------------
// Kernel 2: 768 blocks x 32 threads
//   blocks   0.. 63 : forward chunk 0 (t=1..127), vector chain
//   blocks  64..639 : forward basis chunks c=1..3, 3 basis rows per warp
//   blocks 640..703 : Viterbi forward + backtrace (exact)
//   blocks 704..767 : gold-path score + label_flat copy
// ---------------------------------------------------------------------------
__global__ void crf_kernel(const int* __restrict__ label,
                           const int* __restrict__ mask,
                           const float* __restrict__ startT,
                           const float* __restrict__ endT,
                           const float* __restrict__ trans,
                           float* __restrict__ out) {
    __shared__ unsigned char bp[(S - 1) * L];  // Viterbi backpointers

    int blk = blockIdx.x;
    int lane = threadIdx.x;
    int jj = lane % 9;

    if (blk < 64) {
        // ---------- forward chunk 0: t = 1..127, normal-space vector ----------
        int b = blk;
        const float* emb = g_em + (long)b * S * L;
        const int* mb = mask + b * S;

        float E[9];
#pragma unroll
        for (int i = 0; i < 9; i++) E[i] = __expf(trans[i * 9 + jj]);

        float p = __expf(startT[jj] + emb[jj]);
        float logacc = 0.f;

        float cur[8]; int mcur[8];
#pragma unroll
        for (int k = 0; k < 8; k++) { cur[k] = emb[(1 + k) * 9 + jj]; mcur[k] = mb[1 + k]; }

        int tb = 1;
        for (; tb + 8 <= CH; tb += 8) {
            float w[8];
#pragma unroll
            for (int k = 0; k < 8; k++) w[k] = __expf(cur[k]);
            float nxt[8]; int mnxt[8];
#pragma unroll
            for (int k = 0; k < 8; k++) {
                int t2 = tb + 8 + k;
                if (t2 < CH) { nxt[k] = emb[t2 * 9 + jj]; mnxt[k] = mb[t2]; }
                else         { nxt[k] = 0.f;              mnxt[k] = 0; }
            }
#pragma unroll
            for (int k = 0; k < 8; k++) {
                float p0 = __shfl_sync(FULL, p, 0), p1 = __shfl_sync(FULL, p, 1);
                float p2 = __shfl_sync(FULL, p, 2), p3 = __shfl_sync(FULL, p, 3);
                float p4 = __shfl_sync(FULL, p, 4), p5 = __shfl_sync(FULL, p, 5);
                float p6 = __shfl_sync(FULL, p, 6), p7 = __shfl_sync(FULL, p, 7);
                float p8 = __shfl_sync(FULL, p, 8);
                float s01 = fmaf(p0, E[0], p1 * E[1]);
                float s23 = fmaf(p2, E[2], p3 * E[3]);
                float s45 = fmaf(p4, E[4], p5 * E[5]);
                float s67 = fmaf(p6, E[6], p7 * E[7]);
                float s = ((s01 + s23) + (s45 + s67)) + p8 * E[8];
                float pn = s * w[k];
                p = (mcur[k] > 0) ? pn : p;
                int t = tb + k;
                if ((t & 15) == 0) {
                    float r = __shfl_sync(FULL, p, 0);
                    logacc += __logf(r);
                    p *= __fdividef(1.0f, r);
                }
            }
#pragma unroll
            for (int k = 0; k < 8; k++) { cur[k] = nxt[k]; mcur[k] = mnxt[k]; }
        }
        // tail: t = 121..127 (7 steps)
#pragma unroll
        for (int k = 0; k < 7; k++) {
            float w = __expf(cur[k]);
            float p0 = __shfl_sync(FULL, p, 0), p1 = __shfl_sync(FULL, p, 1);
            float p2 = __shfl_sync(FULL, p, 2), p3 = __shfl_sync(FULL, p, 3);
            float p4 = __shfl_sync(FULL, p, 4), p5 = __shfl_sync(FULL, p, 5);
            float p6 = __shfl_sync(FULL, p, 6), p7 = __shfl_sync(FULL, p, 7);
            float p8 = __shfl_sync(FULL, p, 8);
            float s01 = fmaf(p0, E[0], p1 * E[1]);
            float s23 = fmaf(p2, E[2], p3 * E[3]);
            float s45 = fmaf(p4, E[4], p5 * E[5]);
            float s67 = fmaf(p6, E[6], p7 * E[7]);
            float s = ((s01 + s23) + (s45 + s67)) + p8 * E[8];
            float pn = s * w;
            p = (mcur[k] > 0) ? pn : p;
        }
        if (lane < 9) {
            g_q[b][0][0][jj] = p;
            if (jj == 0) g_lac[b][0][0] = logacc;
        }

    } else if (blk < 640) {
        // ---------- forward basis chunks: 3 rows per warp ----------
        int idx = blk - 64;
        int b = idx / 9;
        int rem = idx % 9;
        int c = 1 + rem / 3;      // chunk 1..3
        int rg = rem % 3;         // row triple
        int g = lane / 9;         // group 0..2 (lanes 27..31 inactive)
        int r = rg * 3 + g;       // basis row
        int base = g * 9;

        const float* emb = g_em + (long)b * S * L;
        const int* mb = mask + b * S;
        int t0 = c * CH;

        float E[9];
#pragma unroll
        for (int i = 0; i < 9; i++) E[i] = __expf(trans[i * 9 + jj]);

        float p = (jj == (r % 9)) ? 1.f : 0.f;
        float logacc = 0.f;

        float cur[8]; int mcur[8];
#pragma unroll
        for (int k = 0; k < 8; k++) { cur[k] = emb[(t0 + k) * 9 + jj]; mcur[k] = mb[t0 + k]; }

        for (int tb = t0; tb < t0 + CH; tb += 8) {
            float w[8];
#pragma unroll
            for (int k = 0; k < 8; k++) w[k] = __expf(cur[k]);
            float nxt[8]; int mnxt[8];
#pragma unroll
            for (int k = 0; k < 8; k++) {
                int t2 = tb + 8 + k;
                if (t2 < t0 + CH) { nxt[k] = emb[t2 * 9 + jj]; mnxt[k] = mb[t2]; }
                else              { nxt[k] = 0.f;              mnxt[k] = 0; }
            }
#pragma unroll
            for (int k = 0; k < 8; k++) {
                float p0 = __shfl_sync(FULL, p, base + 0), p1 = __shfl_sync(FULL, p, base + 1);
                float p2 = __shfl_sync(FULL, p, base + 2), p3 = __shfl_sync(FULL, p, base + 3);
                float p4 = __shfl_sync(FULL, p, base + 4), p5 = __shfl_sync(FULL, p, base + 5);
                float p6 = __shfl_sync(FULL, p, base + 6), p7 = __shfl_sync(FULL, p, base + 7);
                float p8 = __shfl_sync(FULL, p, base + 8);
                float s01 = fmaf(p0, E[0], p1 * E[1]);
                float s23 = fmaf(p2, E[2], p3 * E[3]);
                float s45 = fmaf(p4, E[4], p5 * E[5]);
                float s67 = fmaf(p6, E[6], p7 * E[7]);
                float s = ((s01 + s23) + (s45 + s67)) + p8 * E[8];
                float pn = s * w[k];
                p = (mcur[k] > 0) ? pn : p;
                int t = tb + k;
                if ((t & 15) == 0) {
                    // renorm by this row's diagonal entry (starts at 1, stays > 0)
                    float rv = __shfl_sync(FULL, p, base + (r % 9));
                    logacc += __logf(rv);
                    p *= __fdividef(1.0f, rv);
                }
            }
#pragma unroll
            for (int k = 0; k < 8; k++) { cur[k] = nxt[k]; mcur[k] = mnxt[k]; }
        }

        if (lane < 27) {
            g_q[b][c][r][jj] = p;
            if (jj == 0) g_lac[b][c][r] = logacc;
        }

    } else if (blk < 704) {
        // ---------- Viterbi decode (bit-exact, sequential) ----------
        int b = blk - 640;
        const float* emb = g_em + (long)b * S * L;
        float Tc[9];
#pragma unroll
        for (int i = 0; i < 9; i++) Tc[i] = trans[i * 9 + jj];
        float v = startT[jj] + emb[jj];

        float cur[8];
#pragma unroll
        for (int k = 0; k < 8; k++) cur[k] = emb[(1 + k) * 9 + jj];

        int tb = 1;
        for (; tb + 8 <= S; tb += 8) {
            float nxt[8];
#pragma unroll
            for (int k = 0; k < 8; k++) {
                int t2 = tb + 8 + k;
                nxt[k] = (t2 < S) ? emb[t2 * 9 + jj] : 0.f;
            }
#pragma unroll
            for (int k = 0; k < 8; k++) {
                float e = cur[k];
                float vi[9];
#pragma unroll
                for (int i = 0; i < 9; i++)
                    vi[i] = (__shfl_sync(FULL, v, i) + Tc[i]) + e;  // ref op order
                float a01 = fmaxf(vi[0], vi[1]);
                float a23 = fmaxf(vi[2], vi[3]);
                float a45 = fmaxf(vi[4], vi[5]);
                float a67 = fmaxf(vi[6], vi[7]);
                float M = fmaxf(fmaxf(fmaxf(a01, a23), fmaxf(a45, a67)), vi[8]);
                int arg = 8;                                        // first-occurrence
#pragma unroll
                for (int i = 7; i >= 0; i--) arg = (vi[i] == M) ? i : arg;
                if (lane < 9) bp[(tb + k - 1) * 9 + jj] = (unsigned char)arg;
                v = M;
            }
#pragma unroll
            for (int k = 0; k < 8; k++) cur[k] = nxt[k];
        }
#pragma unroll
        for (int k = 0; k < 7; k++) {                               // t = 505..511
            float e = cur[k];
            float vi[9];
#pragma unroll
            for (int i = 0; i < 9; i++)
                vi[i] = (__shfl_sync(FULL, v, i) + Tc[i]) + e;
            float a01 = fmaxf(vi[0], vi[1]);
            float a23 = fmaxf(vi[2], vi[3]);
            float a45 = fmaxf(vi[4], vi[5]);
            float a67 = fmaxf(vi[6], vi[7]);
            float M = fmaxf(fmaxf(fmaxf(a01, a23), fmaxf(a45, a67)), vi[8]);
            int arg = 8;
#pragma unroll
            for (int i = 7; i >= 0; i--) arg = (vi[i] == M) ? i : arg;
            if (lane < 9) bp[(tb + k - 1) * 9 + jj] = (unsigned char)arg;
            v = M;
        }
        __syncwarp();

        float fj = v + endT[jj];
        float fv[9];
#pragma unroll
        for (int i = 0; i < 9; i++) fv[i] = __shfl_sync(FULL, fj, i);

        if (lane == 0) {
            float best = fv[0];
            int tag = 0;
#pragma unroll
            for (int i = 1; i < 9; i++)
                if (fv[i] > best) { best = fv[i]; tag = i; }
            const int* lb = label + b * S;
            float* pout = out + 2 + (long)b * S;
            float cnt = 0.f;
            {
                int lab = lb[S - 1];
                int pv = (lab > 0) ? tag : 0;
                pout[S - 1] = (float)pv;
                cnt += (pv == lab) ? 1.f : 0.f;
            }
            for (int t = S - 2; t >= 0; t--) {
                tag = bp[t * 9 + tag];
                int lab = lb[t];
                int pv = (lab > 0) ? tag : 0;
                pout[t] = (float)pv;
                cnt += (pv == lab) ? 1.f : 0.f;
            }
            g_corr[b] = cnt;
        }

    } else {
        // ---------- gold path score (masked scan) + label copy ----------
        int b = blk - 704;
        const int* lb = label + b * S;
        const int* mb = mask + b * S;
        const float* emb = g_em + (long)b * S * L;
        int t0 = lane * 16;

        int ll = -1;
#pragma unroll
        for (int k = 0; k < 16; k++) {
            int t = t0 + k;
            if ((t == 0) | (mb[t] > 0)) ll = t;
        }
        int inc = ll;
#pragma unroll
        for (int o = 1; o < 32; o <<= 1) {
            int vv = __shfl_up_sync(FULL, inc, o);
            if (lane >= o) inc = max(inc, vv);
        }
        int exc = __shfl_up_sync(FULL, inc, 1);
        if (lane == 0) exc = -1;
        int lastAll = __shfl_sync(FULL, inc, 31);

        float sc = 0.f;
        int prevIdx = exc;
#pragma unroll
        for (int k = 0; k < 16; k++) {
            int t = t0 + k;
            int mt = mb[t];
            int tg = lb[t];
            if (t >= 1) {
                int pt = lb[prevIdx];
                float s = trans[pt * 9 + tg] + emb[t * 9 + tg];
                sc += s * (float)mt;
            }
            if ((t == 0) | (mt > 0)) prevIdx = t;
        }
#pragma unroll
        for (int o = 16; o > 0; o >>= 1) sc += __shfl_xor_sync(FULL, sc, o);

        if (lane == 0) {
            int tg0 = lb[0];
            g_score[b] = startT[tg0] + emb[tg0] + sc + endT[lb[lastAll]];
        }

        float* lout = out + 2 + (long)B * S;
        for (int t = lane; t < S; t += 32)
            lout[(long)b * S + t] = (float)lb[t];
    }
}

// ---------------------------------------------------------------------------
// Kernel 3: per-batch combine of forward chunks -> logZ   (64 blocks x 32)
// ---------------------------------------------------------------------------
__global__ void fwd_combine_kernel(const float* __restrict__ endT,
                                   float* __restrict__ dummy) {
    int b = blockIdx.x;
    int lane = threadIdx.x;
    int jj = lane % 9;

    float L = g_lac[b][0][0] + __logf(g_q[b][0][0][jj]);

#pragma unroll
    for (int c = 1; c <= 3; c++) {
        float Lr[9];
#pragma unroll
        for (int i = 0; i < 9; i++) Lr[i] = __shfl_sync(FULL, L, i);
        float tr[9];
#pragma unroll
        for (int r = 0; r < 9; r++) {
            float q = g_q[b][c][r][jj];
            tr[r] = Lr[r] + g_lac[b][c][r] + __logf(fmaxf(q, 1e-38f));
        }
        float m = tr[0];
#pragma unroll
        for (int r = 1; r < 9; r++) m = fmaxf(m, tr[r]);
        float sum = 0.f;
#pragma unroll
        for (int r = 0; r < 9; r++) sum += __expf(tr[r] - m);
        L = m + __logf(sum);
    }

    float F = L + endT[jj];
    float Fv[9];
#pragma unroll
    for (int i = 0; i < 9; i++) Fv[i] = __shfl_sync(FULL, F, i);
    float m = Fv[0];
#pragma unroll
    for (int i = 1; i < 9; i++) m = fmaxf(m, Fv[i]);
    float sum = 0.f;
#pragma unroll
    for (int i = 0; i < 9; i++) sum += __expf(Fv[i] - m);
    if (lane == 0) g_logZ[b] = m + __logf(sum);
}

// ---------------------------------------------------------------------------
// Kernel 4: finalize loss & correct
// ---------------------------------------------------------------------------
__global__ void fin_kernel(float* __restrict__ out) {
    __shared__ float sd[64], sc[64];
    int i = threadIdx.x;
    sd[i] = g_score[i] - g_logZ[i];
    sc[i] = g_corr[i];
    __syncthreads();
    if (i == 0) {
        float s = 0.f, c = 0.f;
        for (int k = 0; k < 64; k++) { s += sd[k]; c += sc[k]; }
        out[0] = -s / (float)B;
        out[1] = c;
    }
}

// ---------------------------------------------------------------------------
extern "C" void kernel_launch(void* const* d_in, const int* in_sizes, int n_in,
                              void* d_out, int out_size) {
    const float* hidden = (const float*)d_in[0];
    const int*   label  = (const int*)d_in[1];
    const int*   mask   = (const int*)d_in[2];
    const float* W      = (const float*)d_in[3];
    const float* bias   = (const float*)d_in[4];
    const float* startT = (const float*)d_in[5];
    const float* endT   = (const float*)d_in[6];
    const float* trans  = (const float*)d_in[7];
    float* out = (float*)d_out;

    emis_kernel<<<1024, 256>>>(hidden, W, bias);
    crf_kernel<<<768, 32>>>(label, mask, startT, endT, trans, out);
    fwd_combine_kernel<<<64, 32>>>(endT, out);
    fin_kernel<<<1, 64>>>(out);
}

// round 5
// speedup vs baseline: 1.0220x; 1.0220x over previous
#include <cuda_runtime.h>
#include <cuda_bf16.h>

#define FULL 0xffffffffu

static constexpr int B = 64;
static constexpr int S = 512;
static constexpr int H = 768;
static constexpr int L = 9;

__device__ float g_em[B * S * L];     // [b][t][j]
__device__ float g_score[B];
__device__ float g_logZ[B];
__device__ float g_corr[B];
__device__ int   g_cnt[32];           // per-timestep-chunk production counters (target 64)
__device__ unsigned g_done;           // finished crf warps (target 192)

// Wait until emission chunks [0, need) are produced. Register fast-path.
__device__ __forceinline__ void wait_chunks(int& ready, int need) {
    while (ready < need) {
        if (*(volatile int*)&g_cnt[ready] == 64) { ready++; __threadfence(); }
        else __nanosleep(64);
    }
}

// ---------------------------------------------------------------------------
// Fused kernel. Grid = 64 crf blocks + 2048 emis blocks (t-major), 256 thr.
// ---------------------------------------------------------------------------
__global__ void __launch_bounds__(256, 4)
fused_kernel(const float* __restrict__ hidden,
             const int* __restrict__ label,
             const int* __restrict__ mask,
             const float* __restrict__ W,
             const float* __restrict__ bias,
             const float* __restrict__ startT,
             const float* __restrict__ endT,
             const float* __restrict__ trans,
             float* __restrict__ out) {
    __shared__ float sWT[L * H];                 // emis: W transposed [j][h]
    __shared__ unsigned char bp[(S - 1) * L];    // vit: backpointers
    __shared__ unsigned char comp[255 * L];      // vit: 2-step composed pointers
    __shared__ unsigned char etag[256];          // vit: tags at even t

    int bid = blockIdx.x;

    if (bid >= 64) {
        // =============== emissions producer (t-major order) ===============
        int e = bid - 64;
        int tc = e >> 6;          // timestep chunk 0..31 (16 rows each)
        int b  = e & 63;

        for (int i = threadIdx.x; i < L * H; i += 256) {
            int j = i / H, h = i - j * H;
            sWT[i] = W[h * L + j];
        }
        __syncthreads();

        int warp = threadIdx.x >> 5;
        int lane = threadIdx.x & 31;
        long row0 = (long)b * S + tc * 16 + warp * 2;
        const float* h0 = hidden + row0 * H;

        float acc0[9], acc1[9];
#pragma unroll
        for (int j = 0; j < 9; j++) { acc0[j] = 0.f; acc1[j] = 0.f; }

#pragma unroll
        for (int k = 0; k < 6; k++) {
            int hb = k * 128 + lane * 4;
            float4 x0 = *(const float4*)(h0 + hb);
            float4 x1 = *(const float4*)(h0 + H + hb);
#pragma unroll
            for (int j = 0; j < 9; j++) {
                float4 w4 = *(const float4*)(sWT + j * H + hb);
                acc0[j] = fmaf(x0.x, w4.x, acc0[j]);
                acc0[j] = fmaf(x0.y, w4.y, acc0[j]);
                acc0[j] = fmaf(x0.z, w4.z, acc0[j]);
                acc0[j] = fmaf(x0.w, w4.w, acc0[j]);
                acc1[j] = fmaf(x1.x, w4.x, acc1[j]);
                acc1[j] = fmaf(x1.y, w4.y, acc1[j]);
                acc1[j] = fmaf(x1.z, w4.z, acc1[j]);
                acc1[j] = fmaf(x1.w, w4.w, acc1[j]);
            }
        }

#pragma unroll
        for (int j = 0; j < 9; j++) {
#pragma unroll
            for (int o = 16; o > 0; o >>= 1) {
                acc0[j] += __shfl_xor_sync(FULL, acc0[j], o);
                acc1[j] += __shfl_xor_sync(FULL, acc1[j], o);
            }
        }

        if (lane == 0) {
            float v[18];
#pragma unroll
            for (int j = 0; j < 9; j++) {
                float bb = bias[j];
                v[j] = acc0[j] + bb;
                v[9 + j] = acc1[j] + bb;
            }
            float2* dst = (float2*)(g_em + row0 * 9);  // row0 even -> 8B aligned
#pragma unroll
            for (int q = 0; q < 9; q++) dst[q] = make_float2(v[2 * q], v[2 * q + 1]);
        }
        __syncthreads();
        if (threadIdx.x == 0) { __threadfence(); atomicAdd(&g_cnt[tc], 1); }
        return;
    }

    // ==================== crf consumer block (batch b) ====================
    int b = bid;
    int warp = threadIdx.x >> 5;
    if (warp >= 3) return;
    int lane = threadIdx.x & 31;
    int jj = lane % 9;
    const float* emb = g_em + (long)b * S * L;

    if (warp == 0) {
        // ---------- forward algorithm (logZ), normal space ----------
        const int* mb = mask + b * S;
        float E[9];
#pragma unroll
        for (int i = 0; i < 9; i++) E[i] = __expf(trans[i * 9 + jj]);
        float eend = __expf(endT[jj]);

        int ready = 0;
        wait_chunks(ready, 1);

        float p = __expf(startT[jj] + __ldcv(emb + jj));
        float logacc = 0.f;

        float cur[8]; int mcur[8];
#pragma unroll
        for (int k = 0; k < 8; k++) { cur[k] = __ldcv(emb + (1 + k) * 9 + jj); mcur[k] = mb[1 + k]; }

        int tb = 1;
        for (; tb + 8 <= S; tb += 8) {
            float w[8];
#pragma unroll
            for (int k = 0; k < 8; k++) w[k] = __expf(cur[k]);

            int tmax = tb + 15 < S - 1 ? tb + 15 : S - 1;
            wait_chunks(ready, (tmax >> 4) + 1);

            float nxt[8]; int mnxt[8];
#pragma unroll
            for (int k = 0; k < 8; k++) {
                int t2 = tb + 8 + k;
                if (t2 < S) { nxt[k] = __ldcv(emb + t2 * 9 + jj); mnxt[k] = mb[t2]; }
                else        { nxt[k] = 0.f;                       mnxt[k] = 0; }
            }
#pragma unroll
            for (int k = 0; k < 8; k++) {
                float p0 = __shfl_sync(FULL, p, 0), p1 = __shfl_sync(FULL, p, 1);
                float p2 = __shfl_sync(FULL, p, 2), p3 = __shfl_sync(FULL, p, 3);
                float p4 = __shfl_sync(FULL, p, 4), p5 = __shfl_sync(FULL, p, 5);
                float p6 = __shfl_sync(FULL, p, 6), p7 = __shfl_sync(FULL, p, 7);
                float p8 = __shfl_sync(FULL, p, 8);
                float s01 = fmaf(p0, E[0], p1 * E[1]);
                float s23 = fmaf(p2, E[2], p3 * E[3]);
                float s45 = fmaf(p4, E[4], p5 * E[5]);
                float s67 = fmaf(p6, E[6], p7 * E[7]);
                float s = ((s01 + s23) + (s45 + s67)) + p8 * E[8];
                float pn = s * w[k];
                p = (mcur[k] > 0) ? pn : p;
                int t = tb + k;
                if ((t & 15) == 0) {
                    float r = __shfl_sync(FULL, p, 0);
                    logacc += __logf(r);
                    p *= __fdividef(1.0f, r);
                }
            }
#pragma unroll
            for (int k = 0; k < 8; k++) { cur[k] = nxt[k]; mcur[k] = mnxt[k]; }
        }
#pragma unroll
        for (int k = 0; k < 7; k++) {     // t = 505..511
            float w = __expf(cur[k]);
            float p0 = __shfl_sync(FULL, p, 0), p1 = __shfl_sync(FULL, p, 1);
            float p2 = __shfl_sync(FULL, p, 2), p3 = __shfl_sync(FULL, p, 3);
            float p4 = __shfl_sync(FULL, p, 4), p5 = __shfl_sync(FULL, p, 5);
            float p6 = __shfl_sync(FULL, p, 6), p7 = __shfl_sync(FULL, p, 7);
            float p8 = __shfl_sync(FULL, p, 8);
            float s01 = fmaf(p0, E[0], p1 * E[1]);
            float s23 = fmaf(p2, E[2], p3 * E[3]);
            float s45 = fmaf(p4, E[4], p5 * E[5]);
            float s67 = fmaf(p6, E[6], p7 * E[7]);
            float s = ((s01 + s23) + (s45 + s67)) + p8 * E[8];
            float pn = s * w;
            p = (mcur[k] > 0) ? pn : p;
        }

        float f = p * eend;
        float tot = 0.f;
#pragma unroll
        for (int i = 0; i < 9; i++) tot += __shfl_sync(FULL, f, i);
        if (lane == 0) g_logZ[b] = logacc + __logf(tot);

    } else if (warp == 1) {
        // ---------- Viterbi decode (bit-exact, sequential) ----------
        float Tc[9];
#pragma unroll
        for (int i = 0; i < 9; i++) Tc[i] = trans[i * 9 + jj];

        int ready = 0;
        wait_chunks(ready, 1);

        float v = startT[jj] + __ldcv(emb + jj);

        float cur[8];
#pragma unroll
        for (int k = 0; k < 8; k++) cur[k] = __ldcv(emb + (1 + k) * 9 + jj);

        int tb = 1;
        for (; tb + 8 <= S; tb += 8) {
            int tmax = tb + 15 < S - 1 ? tb + 15 : S - 1;
            wait_chunks(ready, (tmax >> 4) + 1);

            float nxt[8];
#pragma unroll
            for (int k = 0; k < 8; k++) {
                int t2 = tb + 8 + k;
                nxt[k] = (t2 < S) ? __ldcv(emb + t2 * 9 + jj) : 0.f;
            }
#pragma unroll
            for (int k = 0; k < 8; k++) {
                float e = cur[k];
                float vi[9];
#pragma unroll
                for (int i = 0; i < 9; i++)
                    vi[i] = (__shfl_sync(FULL, v, i) + Tc[i]) + e;  // ref op order
                float a01 = fmaxf(vi[0], vi[1]);
                float a23 = fmaxf(vi[2], vi[3]);
                float a45 = fmaxf(vi[4], vi[5]);
                float a67 = fmaxf(vi[6], vi[7]);
                float M = fmaxf(fmaxf(fmaxf(a01, a23), fmaxf(a45, a67)), vi[8]);
                int arg = 8;                                        // first-occurrence
#pragma unroll
                for (int i = 7; i >= 0; i--) arg = (vi[i] == M) ? i : arg;
                if (lane < 9) bp[(tb + k - 1) * 9 + jj] = (unsigned char)arg;
                v = M;
            }
#pragma unroll
            for (int k = 0; k < 8; k++) cur[k] = nxt[k];
        }
#pragma unroll
        for (int k = 0; k < 7; k++) {                               // t = 505..511
            float e = cur[k];
            float vi[9];
#pragma unroll
            for (int i = 0; i < 9; i++)
                vi[i] = (__shfl_sync(FULL, v, i) + Tc[i]) + e;
            float a01 = fmaxf(vi[0], vi[1]);
            float a23 = fmaxf(vi[2], vi[3]);
            float a45 = fmaxf(vi[4], vi[5]);
            float a67 = fmaxf(vi[6], vi[7]);
            float M = fmaxf(fmaxf(fmaxf(a01, a23), fmaxf(a45, a67)), vi[8]);
            int arg = 8;
#pragma unroll
            for (int i = 7; i >= 0; i--) arg = (vi[i] == M) ? i : arg;
            if (lane < 9) bp[(tb + k - 1) * 9 + jj] = (unsigned char)arg;
            v = M;
        }
        __syncwarp();

        // final tag (all lanes compute identically)
        float fj = v + endT[jj];
        float fv[9];
#pragma unroll
        for (int i = 0; i < 9; i++) fv[i] = __shfl_sync(FULL, fj, i);
        float best = fv[0];
        int tag511 = 0;
#pragma unroll
        for (int i = 1; i < 9; i++)
            if (fv[i] > best) { best = fv[i]; tag511 = i; }   // first-max tie

        // build 2-step composed pointers C(t)[j] = P(t-1)[P(t)[j]], even t in [2,510]
        for (int idx = lane; idx < 255 * 9; idx += 32) {
            int ci = idx / 9;
            int j = idx - ci * 9;
            int t = 2 * ci + 2;
            comp[idx] = bp[(t - 2) * 9 + bp[(t - 1) * 9 + j]];
        }
        __syncwarp();

        // chase even tags (lane 0): 255 dependent hops instead of 511
        if (lane == 0) {
            int cur_t = bp[510 * 9 + tag511];   // tag at t=510
            etag[255] = (unsigned char)cur_t;
            for (int t = 510; t >= 2; t -= 2) {
                cur_t = comp[((t - 2) >> 1) * 9 + cur_t];
                etag[(t - 2) >> 1] = (unsigned char)cur_t;
            }
        }
        __syncwarp();

        // fill odd tags + outputs + correct count (warp-parallel)
        const int* lb = label + b * S;
        float* pout = out + 2 + (long)b * S;
        float cnt = 0.f;
        for (int t = lane; t < S; t += 32) {
            int tg;
            if (t == 511) tg = tag511;
            else if ((t & 1) == 0) tg = etag[t >> 1];
            else tg = bp[t * 9 + etag[(t + 1) >> 1]];
            int lab = lb[t];
            int pv = (lab > 0) ? tg : 0;
            pout[t] = (float)pv;
            cnt += (pv == lab) ? 1.f : 0.f;
        }
#pragma unroll
        for (int o = 16; o > 0; o >>= 1) cnt += __shfl_xor_sync(FULL, cnt, o);
        if (lane == 0) g_corr[b] = cnt;

    } else {
        // ---------- gold path score (masked scan) + label copy ----------
        const int* lb = label + b * S;
        const int* mb = mask + b * S;
        int t0 = lane * 16;

        int ready = 0;
        wait_chunks(ready, 32);   // need full batch

        int ll = -1;
#pragma unroll
        for (int k = 0; k < 16; k++) {
            int t = t0 + k;
            if ((t == 0) | (mb[t] > 0)) ll = t;
        }
        int inc = ll;
#pragma unroll
        for (int o = 1; o < 32; o <<= 1) {
            int vv = __shfl_up_sync(FULL, inc, o);
            if (lane >= o) inc = max(inc, vv);
        }
        int exc = __shfl_up_sync(FULL, inc, 1);
        if (lane == 0) exc = -1;
        int lastAll = __shfl_sync(FULL, inc, 31);

        float sc = 0.f;
        int prevIdx = exc;
#pragma unroll
        for (int k = 0; k < 16; k++) {
            int t = t0 + k;
            int mt = mb[t];
            int tg = lb[t];
            if (t >= 1) {
                int pt = lb[prevIdx];
                float s = trans[pt * 9 + tg] + __ldcv(emb + t * 9 + tg);
                sc += s * (float)mt;
            }
            if ((t == 0) | (mt > 0)) prevIdx = t;
        }
#pragma unroll
        for (int o = 16; o > 0; o >>= 1) sc += __shfl_xor_sync(FULL, sc, o);

        if (lane == 0) {
            int tg0 = lb[0];
            g_score[b] = startT[tg0] + __ldcv(emb + tg0) + sc + endT[lb[lastAll]];
        }

        float* lout = out + 2 + (long)B * S;
        for (int t = lane; t < S; t += 32)
            lout[(long)b * S + t] = (float)lb[t];
    }

    // ---------- per-warp done accounting; last warp finalizes + resets ----------
    __threadfence();
    unsigned my = 0;
    if (lane == 0) my = atomicAdd(&g_done, 1u);
    my = __shfl_sync(FULL, my, 0);
    if (my == 191u) {
        float d = 0.f, c = 0.f;
#pragma unroll
        for (int k = lane; k < 64; k += 32) {
            d += __ldcg(&g_score[k]) - __ldcg(&g_logZ[k]);
            c += __ldcg(&g_corr[k]);
        }
#pragma unroll
        for (int o = 16; o > 0; o >>= 1) {
            d += __shfl_xor_sync(FULL, d, o);
            c += __shfl_xor_sync(FULL, c, o);
        }
        if (lane == 0) {
            out[0] = -d / (float)B;
            out[1] = c;
            g_done = 0;
        }
        g_cnt[lane] = 0;   // lanes 0..31 reset all 32 chunk counters
    }
}

// ---------------------------------------------------------------------------
extern "C" void kernel_launch(void* const* d_in, const int* in_sizes, int n_in,
                              void* d_out, int out_size) {
    const float* hidden = (const float*)d_in[0];
    const int*   label  = (const int*)d_in[1];
    const int*   mask   = (const int*)d_in[2];
    const float* W      = (const float*)d_in[3];
    const float* bias   = (const float*)d_in[4];
    const float* startT = (const float*)d_in[5];
    const float* endT   = (const float*)d_in[6];
    const float* trans  = (const float*)d_in[7];
    float* out = (float*)d_out;

    fused_kernel<<<64 + 2048, 256>>>(hidden, label, mask, W, bias,
                                     startT, endT, trans, out);
}

// round 7
// speedup vs baseline: 1.1063x; 1.0825x over previous
#include <cuda_runtime.h>
#include <cuda_bf16.h>

#define FULL 0xffffffffu

static constexpr int B = 64;
static constexpr int S = 512;
static constexpr int H = 768;
static constexpr int L = 9;

__device__ float g_em[B * S * L];     // [b][t][j]
__device__ float g_score[B];
__device__ float g_logZ[B];
__device__ float g_corr[B];
__device__ unsigned g_done;           // finished crf warps (target 192)

// ---------------------------------------------------------------------------
// Kernel 1: emissions = hidden @ W + b   (bit-identical to round-3, 33 us)
// block 256 (8 warps), 2 rows per warp, float4 loads; grid = 2048
// ---------------------------------------------------------------------------
__global__ void __launch_bounds__(256) emis_kernel(const float* __restrict__ hidden,
                                                   const float* __restrict__ W,
                                                   const float* __restrict__ bias) {
    __shared__ float sWT[L * H];  // [j][h], 27648 B
    for (int i = threadIdx.x; i < L * H; i += 256) {
        int j = i / H, h = i - j * H;
        sWT[i] = W[h * L + j];
    }
    __syncthreads();

    int warp = threadIdx.x >> 5;
    int lane = threadIdx.x & 31;
    long row0 = (long)(blockIdx.x * 8 + warp) * 2;
    const float* h0 = hidden + row0 * H;

    float acc0[9], acc1[9];
#pragma unroll
    for (int j = 0; j < 9; j++) { acc0[j] = 0.f; acc1[j] = 0.f; }

#pragma unroll
    for (int k = 0; k < 6; k++) {
        int hb = k * 128 + lane * 4;
        float4 x0 = *(const float4*)(h0 + hb);
        float4 x1 = *(const float4*)(h0 + H + hb);
#pragma unroll
        for (int j = 0; j < 9; j++) {
            float4 w4 = *(const float4*)(sWT + j * H + hb);
            acc0[j] = fmaf(x0.x, w4.x, acc0[j]);
            acc0[j] = fmaf(x0.y, w4.y, acc0[j]);
            acc0[j] = fmaf(x0.z, w4.z, acc0[j]);
            acc0[j] = fmaf(x0.w, w4.w, acc0[j]);
            acc1[j] = fmaf(x1.x, w4.x, acc1[j]);
            acc1[j] = fmaf(x1.y, w4.y, acc1[j]);
            acc1[j] = fmaf(x1.z, w4.z, acc1[j]);
            acc1[j] = fmaf(x1.w, w4.w, acc1[j]);
        }
    }

#pragma unroll
    for (int j = 0; j < 9; j++) {
#pragma unroll
        for (int o = 16; o > 0; o >>= 1) {
            acc0[j] += __shfl_xor_sync(FULL, acc0[j], o);
            acc1[j] += __shfl_xor_sync(FULL, acc1[j], o);
        }
    }

    if (lane == 0) {
        float v[18];
#pragma unroll
        for (int j = 0; j < 9; j++) {
            float bb = bias[j];
            v[j] = acc0[j] + bb;
            v[9 + j] = acc1[j] + bb;
        }
        float2* dst = (float2*)(g_em + row0 * 9);  // row0 even -> 8B aligned
#pragma unroll
        for (int q = 0; q < 9; q++) dst[q] = make_float2(v[2 * q], v[2 * q + 1]);
    }
}

// ---------------------------------------------------------------------------
// Kernel 2: 64 blocks x 96 threads (one block per batch; all wave-1 resident)
//   warp0: forward DP (logZ)   warp1: Viterbi + fast backtrace   warp2: numerator
// Last finishing warp (of 192) computes loss/correct and resets g_done.
// ---------------------------------------------------------------------------
__global__ void __launch_bounds__(96)
crf_kernel(const int* __restrict__ label,
           const int* __restrict__ mask,
           const float* __restrict__ startT,
           const float* __restrict__ endT,
           const float* __restrict__ trans,
           float* __restrict__ out) {
    __shared__ unsigned char bp[(S - 1) * L];    // backpointers (4599 B)
    __shared__ unsigned char comp[255 * L];      // 2-step composed pointers
    __shared__ unsigned char etag[256];          // tags at even t

    int b = blockIdx.x;
    int warp = threadIdx.x >> 5;
    int lane = threadIdx.x & 31;
    int jj = lane % 9;
    const float* emb = g_em + (long)b * S * L;

    if (warp == 0) {
        // ---------- forward algorithm (logZ), normal space ----------
        const int* mb = mask + b * S;
        float E[9];
#pragma unroll
        for (int i = 0; i < 9; i++) E[i] = __expf(trans[i * 9 + jj]);
        float eend = __expf(endT[jj]);

        float p = __expf(startT[jj] + emb[jj]);
        float logacc = 0.f;

        float cur[8]; int mcur[8];
#pragma unroll
        for (int k = 0; k < 8; k++) { cur[k] = emb[(1 + k) * 9 + jj]; mcur[k] = mb[1 + k]; }

        int tb = 1;
        for (; tb + 8 <= S; tb += 8) {
            float w[8];
#pragma unroll
            for (int k = 0; k < 8; k++) w[k] = __expf(cur[k]);
            float nxt[8]; int mnxt[8];
#pragma unroll
            for (int k = 0; k < 8; k++) {
                int t2 = tb + 8 + k;
                if (t2 < S) { nxt[k] = emb[t2 * 9 + jj]; mnxt[k] = mb[t2]; }
                else        { nxt[k] = 0.f;              mnxt[k] = 0; }
            }
#pragma unroll
            for (int k = 0; k < 8; k++) {
                float p0 = __shfl_sync(FULL, p, 0), p1 = __shfl_sync(FULL, p, 1);
                float p2 = __shfl_sync(FULL, p, 2), p3 = __shfl_sync(FULL, p, 3);
                float p4 = __shfl_sync(FULL, p, 4), p5 = __shfl_sync(FULL, p, 5);
                float p6 = __shfl_sync(FULL, p, 6), p7 = __shfl_sync(FULL, p, 7);
                float p8 = __shfl_sync(FULL, p, 8);
                float s01 = fmaf(p0, E[0], p1 * E[1]);
                float s23 = fmaf(p2, E[2], p3 * E[3]);
                float s45 = fmaf(p4, E[4], p5 * E[5]);
                float s67 = fmaf(p6, E[6], p7 * E[7]);
                float s = ((s01 + s23) + (s45 + s67)) + p8 * E[8];
                float pn = s * w[k];
                p = (mcur[k] > 0) ? pn : p;
                int t = tb + k;
                if ((t & 15) == 0) {
                    float r = __shfl_sync(FULL, p, 0);
                    logacc += __logf(r);
                    p *= __fdividef(1.0f, r);
                }
            }
#pragma unroll
            for (int k = 0; k < 8; k++) { cur[k] = nxt[k]; mcur[k] = mnxt[k]; }
        }
#pragma unroll
        for (int k = 0; k < 7; k++) {     // t = 505..511
            float w = __expf(cur[k]);
            float p0 = __shfl_sync(FULL, p, 0), p1 = __shfl_sync(FULL, p, 1);
            float p2 = __shfl_sync(FULL, p, 2), p3 = __shfl_sync(FULL, p, 3);
            float p4 = __shfl_sync(FULL, p, 4), p5 = __shfl_sync(FULL, p, 5);
            float p6 = __shfl_sync(FULL, p, 6), p7 = __shfl_sync(FULL, p, 7);
            float p8 = __shfl_sync(FULL, p, 8);
            float s01 = fmaf(p0, E[0], p1 * E[1]);
            float s23 = fmaf(p2, E[2], p3 * E[3]);
            float s45 = fmaf(p4, E[4], p5 * E[5]);
            float s67 = fmaf(p6, E[6], p7 * E[7]);
            float s = ((s01 + s23) + (s45 + s67)) + p8 * E[8];
            float pn = s * w;
            p = (mcur[k] > 0) ? pn : p;
        }

        float f = p * eend;
        float tot = 0.f;
#pragma unroll
        for (int i = 0; i < 9; i++) tot += __shfl_sync(FULL, f, i);
        if (lane == 0) g_logZ[b] = logacc + __logf(tot);

    } else if (warp == 1) {
        // ---------- Viterbi decode (bit-exact) + fast backtrace ----------
        float Tc[9];
#pragma unroll
        for (int i = 0; i < 9; i++) Tc[i] = trans[i * 9 + jj];
        float v = startT[jj] + emb[jj];

        float cur[8];
#pragma unroll
        for (int k = 0; k < 8; k++) cur[k] = emb[(1 + k) * 9 + jj];

        int tb = 1;
        for (; tb + 8 <= S; tb += 8) {
            float nxt[8];
#pragma unroll
            for (int k = 0; k < 8; k++) {
                int t2 = tb + 8 + k;
                nxt[k] = (t2 < S) ? emb[t2 * 9 + jj] : 0.f;
            }
#pragma unroll
            for (int k = 0; k < 8; k++) {
                float e = cur[k];
                float vi[9];
#pragma unroll
                for (int i = 0; i < 9; i++)
                    vi[i] = (__shfl_sync(FULL, v, i) + Tc[i]) + e;  // ref op order
                float a01 = fmaxf(vi[0], vi[1]);
                float a23 = fmaxf(vi[2], vi[3]);
                float a45 = fmaxf(vi[4], vi[5]);
                float a67 = fmaxf(vi[6], vi[7]);
                float M = fmaxf(fmaxf(fmaxf(a01, a23), fmaxf(a45, a67)), vi[8]);
                int arg = 8;                                        // first-occurrence
#pragma unroll
                for (int i = 7; i >= 0; i--) arg = (vi[i] == M) ? i : arg;
                if (lane < 9) bp[(tb + k - 1) * 9 + jj] = (unsigned char)arg;
                v = M;
            }
#pragma unroll
            for (int k = 0; k < 8; k++) cur[k] = nxt[k];
        }
#pragma unroll
        for (int k = 0; k < 7; k++) {                               // t = 505..511
            float e = cur[k];
            float vi[9];
#pragma unroll
            for (int i = 0; i < 9; i++)
                vi[i] = (__shfl_sync(FULL, v, i) + Tc[i]) + e;
            float a01 = fmaxf(vi[0], vi[1]);
            float a23 = fmaxf(vi[2], vi[3]);
            float a45 = fmaxf(vi[4], vi[5]);
            float a67 = fmaxf(vi[6], vi[7]);
            float M = fmaxf(fmaxf(fmaxf(a01, a23), fmaxf(a45, a67)), vi[8]);
            int arg = 8;
#pragma unroll
            for (int i = 7; i >= 0; i--) arg = (vi[i] == M) ? i : arg;
            if (lane < 9) bp[(tb + k - 1) * 9 + jj] = (unsigned char)arg;
            v = M;
        }
        __syncwarp();

        // final tag (all lanes compute identically)
        float fj = v + endT[jj];
        float fv[9];
#pragma unroll
        for (int i = 0; i < 9; i++) fv[i] = __shfl_sync(FULL, fj, i);
        float best = fv[0];
        int tag511 = 0;
#pragma unroll
        for (int i = 1; i < 9; i++)
            if (fv[i] > best) { best = fv[i]; tag511 = i; }   // first-max tie

        // build 2-step composed pointers C[t/2-1][j] = P(t-1)[P(t)[j]], even t
        for (int idx = lane; idx < 255 * 9; idx += 32) {
            int ci = idx / 9;
            int j = idx - ci * 9;
            int t = 2 * ci + 2;
            comp[idx] = bp[(t - 2) * 9 + bp[(t - 1) * 9 + j]];
        }
        __syncwarp();

        // chase even tags (lane 0): 255 dependent hops instead of 511
        if (lane == 0) {
            int cur_t = bp[510 * 9 + tag511];   // tag at t=510
            etag[255] = (unsigned char)cur_t;
            for (int t = 510; t >= 2; t -= 2) {
                cur_t = comp[((t - 2) >> 1) * 9 + cur_t];
                etag[(t - 2) >> 1] = (unsigned char)cur_t;
            }
        }
        __syncwarp();

        // fill odd tags + outputs + correct count (warp-parallel)
        const int* lb = label + b * S;
        float* pout = out + 2 + (long)b * S;
        float cnt = 0.f;
        for (int t = lane; t < S; t += 32) {
            int tg;
            if (t == 511) tg = tag511;
            else if ((t & 1) == 0) tg = etag[t >> 1];
            else tg = bp[t * 9 + etag[(t + 1) >> 1]];
            int lab = lb[t];
            int pv = (lab > 0) ? tg : 0;
            pout[t] = (float)pv;
            cnt += (pv == lab) ? 1.f : 0.f;
        }
#pragma unroll
        for (int o = 16; o > 0; o >>= 1) cnt += __shfl_xor_sync(FULL, cnt, o);
        if (lane == 0) g_corr[b] = cnt;

    } else {
        // ---------- gold path score (masked scan) + label copy ----------
        const int* lb = label + b * S;
        const int* mb = mask + b * S;
        int t0 = lane * 16;

        int ll = -1;
#pragma unroll
        for (int k = 0; k < 16; k++) {
            int t = t0 + k;
            if ((t == 0) | (mb[t] > 0)) ll = t;
        }
        int inc = ll;
#pragma unroll
        for (int o = 1; o < 32; o <<= 1) {
            int vv = __shfl_up_sync(FULL, inc, o);
            if (lane >= o) inc = max(inc, vv);
        }
        int exc = __shfl_up_sync(FULL, inc, 1);
        if (lane == 0) exc = -1;
        int lastAll = __shfl_sync(FULL, inc, 31);

        float sc = 0.f;
        int prevIdx = exc;
#pragma unroll
        for (int k = 0; k < 16; k++) {
            int t = t0 + k;
            int mt = mb[t];
            int tg = lb[t];
            if (t >= 1) {
                int pt = lb[prevIdx];
                float s = trans[pt * 9 + tg] + emb[t * 9 + tg];
                sc += s * (float)mt;
            }
            if ((t == 0) | (mt > 0)) prevIdx = t;
        }
#pragma unroll
        for (int o = 16; o > 0; o >>= 1) sc += __shfl_xor_sync(FULL, sc, o);

        if (lane == 0) {
            int tg0 = lb[0];
            g_score[b] = startT[tg0] + emb[tg0] + sc + endT[lb[lastAll]];
        }

        float* lout = out + 2 + (long)B * S;
        for (int t = lane; t < S; t += 32)
            lout[(long)b * S + t] = (float)lb[t];
    }

    // ---------- per-warp done accounting; last warp finalizes + resets ----------
    __threadfence();
    unsigned my = 0;
    if (lane == 0) my = atomicAdd(&g_done, 1u);
    my = __shfl_sync(FULL, my, 0);
    if (my == 191u) {
        float d = 0.f, c = 0.f;
#pragma unroll
        for (int k = lane; k < 64; k += 32) {
            d += __ldcg(&g_score[k]) - __ldcg(&g_logZ[k]);
            c += __ldcg(&g_corr[k]);
        }
#pragma unroll
        for (int o = 16; o > 0; o >>= 1) {
            d += __shfl_xor_sync(FULL, d, o);
            c += __shfl_xor_sync(FULL, c, o);
        }
        if (lane == 0) {
            out[0] = -d / (float)B;
            out[1] = c;
            g_done = 0;   // reset for next graph replay
        }
    }
}

// ---------------------------------------------------------------------------
extern "C" void kernel_launch(void* const* d_in, const int* in_sizes, int n_in,
                              void* d_out, int out_size) {
    const float* hidden = (const float*)d_in[0];
    const int*   label  = (const int*)d_in[1];
    const int*   mask   = (const int*)d_in[2];
    const float* W      = (const float*)d_in[3];
    const float* bias   = (const float*)d_in[4];
    const float* startT = (const float*)d_in[5];
    const float* endT   = (const float*)d_in[6];
    const float* trans  = (const float*)d_in[7];
    float* out = (float*)d_out;

    emis_kernel<<<2048, 256>>>(hidden, W, bias);
    crf_kernel<<<64, 96>>>(label, mask, startT, endT, trans, out);
}

// round 8
// speedup vs baseline: 1.1579x; 1.0466x over previous
#include <cuda_runtime.h>
#include <cuda_bf16.h>

#define FULL 0xffffffffu

static constexpr int B = 64;
static constexpr int S = 512;
static constexpr int H = 768;
static constexpr int L = 9;

__device__ float g_em[B * S * L];     // [b][t][j]
__device__ float g_score[B];
__device__ float g_logZ[B];
__device__ float g_corr[B];
__device__ unsigned g_done;           // finished crf warps (target 192)

// ---------------------------------------------------------------------------
// Kernel 1: emissions = hidden @ W + b
// block 256 (8 warps), 2 rows/warp, float4 loads with 1-iter prefetch.
// grid = 2048.  W transposed [9][768] in smem -> conflict-free LDS.128.
// ---------------------------------------------------------------------------
__global__ void __launch_bounds__(256) emis_kernel(const float* __restrict__ hidden,
                                                   const float* __restrict__ W,
                                                   const float* __restrict__ bias) {
    __shared__ float sWT[L * H];  // [j][h], 27648 B
    for (int i = threadIdx.x; i < L * H; i += 256) {
        int j = i / H, h = i - j * H;
        sWT[i] = W[h * L + j];
    }
    __syncthreads();

    int warp = threadIdx.x >> 5;
    int lane = threadIdx.x & 31;
    long row0 = (long)(blockIdx.x * 8 + warp) * 2;
    const float* h0 = hidden + row0 * H;

    float acc0[9], acc1[9];
#pragma unroll
    for (int j = 0; j < 9; j++) { acc0[j] = 0.f; acc1[j] = 0.f; }

    // double-buffered x loads: keep 4 LDG.128 in flight ahead of the FMAs
    float4 nx0 = *(const float4*)(h0 + lane * 4);
    float4 nx1 = *(const float4*)(h0 + H + lane * 4);

#pragma unroll
    for (int k = 0; k < 6; k++) {
        float4 x0 = nx0, x1 = nx1;
        if (k < 5) {
            int hb = (k + 1) * 128 + lane * 4;
            nx0 = *(const float4*)(h0 + hb);
            nx1 = *(const float4*)(h0 + H + hb);
        }
        int hb = k * 128 + lane * 4;
#pragma unroll
        for (int j = 0; j < 9; j++) {
            float4 w4 = *(const float4*)(sWT + j * H + hb);
            acc0[j] = fmaf(x0.x, w4.x, acc0[j]);
            acc0[j] = fmaf(x0.y, w4.y, acc0[j]);
            acc0[j] = fmaf(x0.z, w4.z, acc0[j]);
            acc0[j] = fmaf(x0.w, w4.w, acc0[j]);
            acc1[j] = fmaf(x1.x, w4.x, acc1[j]);
            acc1[j] = fmaf(x1.y, w4.y, acc1[j]);
            acc1[j] = fmaf(x1.z, w4.z, acc1[j]);
            acc1[j] = fmaf(x1.w, w4.w, acc1[j]);
        }
    }

#pragma unroll
    for (int j = 0; j < 9; j++) {
#pragma unroll
        for (int o = 16; o > 0; o >>= 1) {
            acc0[j] += __shfl_xor_sync(FULL, acc0[j], o);
            acc1[j] += __shfl_xor_sync(FULL, acc1[j], o);
        }
    }

    if (lane == 0) {
        float v[18];
#pragma unroll
        for (int j = 0; j < 9; j++) {
            float bb = bias[j];
            v[j] = acc0[j] + bb;
            v[9 + j] = acc1[j] + bb;
        }
        float2* dst = (float2*)(g_em + row0 * 9);  // row0 even -> 8B aligned
#pragma unroll
        for (int q = 0; q < 9; q++) dst[q] = make_float2(v[2 * q], v[2 * q + 1]);
    }
}

// ---------------------------------------------------------------------------
// Kernel 2: 192 blocks x 32 threads (one role-warp per SM -> full MIO each)
//   blocks   0.. 63 : forward DP (logZ)
//   blocks  64..127 : Viterbi + fast backtrace + predict + correct
//   blocks 128..191 : gold-path score + label_flat copy
// Last finishing warp (of 192) computes loss/correct and resets g_done.
// ---------------------------------------------------------------------------
__global__ void __launch_bounds__(32)
crf_kernel(const int* __restrict__ label,
           const int* __restrict__ mask,
           const float* __restrict__ startT,
           const float* __restrict__ endT,
           const float* __restrict__ trans,
           float* __restrict__ out) {
    __shared__ unsigned char bp[(S - 1) * L];    // backpointers (4599 B)
    __shared__ unsigned char comp[255 * L];      // 2-step composed pointers
    __shared__ unsigned char etag[256];          // tags at even t

    int blk = blockIdx.x;
    int lane = threadIdx.x;
    int jj = lane % 9;

    if (blk < 64) {
        // ---------- forward algorithm (logZ), normal space ----------
        int b = blk;
        const float* emb = g_em + (long)b * S * L;
        const int* mb = mask + b * S;
        float E[9];
#pragma unroll
        for (int i = 0; i < 9; i++) E[i] = __expf(trans[i * 9 + jj]);
        float eend = __expf(endT[jj]);

        float p = __expf(startT[jj] + emb[jj]);
        float logacc = 0.f;

        float cur[8]; int mcur[8];
#pragma unroll
        for (int k = 0; k < 8; k++) { cur[k] = emb[(1 + k) * 9 + jj]; mcur[k] = mb[1 + k]; }

        int tb = 1;
        for (; tb + 8 <= S; tb += 8) {
            float w[8];
#pragma unroll
            for (int k = 0; k < 8; k++) w[k] = __expf(cur[k]);
            float nxt[8]; int mnxt[8];
#pragma unroll
            for (int k = 0; k < 8; k++) {
                int t2 = tb + 8 + k;
                if (t2 < S) { nxt[k] = emb[t2 * 9 + jj]; mnxt[k] = mb[t2]; }
                else        { nxt[k] = 0.f;              mnxt[k] = 0; }
            }
#pragma unroll
            for (int k = 0; k < 8; k++) {
                float p0 = __shfl_sync(FULL, p, 0), p1 = __shfl_sync(FULL, p, 1);
                float p2 = __shfl_sync(FULL, p, 2), p3 = __shfl_sync(FULL, p, 3);
                float p4 = __shfl_sync(FULL, p, 4), p5 = __shfl_sync(FULL, p, 5);
                float p6 = __shfl_sync(FULL, p, 6), p7 = __shfl_sync(FULL, p, 7);
                float p8 = __shfl_sync(FULL, p, 8);
                float s01 = fmaf(p0, E[0], p1 * E[1]);
                float s23 = fmaf(p2, E[2], p3 * E[3]);
                float s45 = fmaf(p4, E[4], p5 * E[5]);
                float s67 = fmaf(p6, E[6], p7 * E[7]);
                float s = ((s01 + s23) + (s45 + s67)) + p8 * E[8];
                float pn = s * w[k];
                p = (mcur[k] > 0) ? pn : p;
                int t = tb + k;
                if ((t & 15) == 0) {
                    float r = __shfl_sync(FULL, p, 0);
                    logacc += __logf(r);
                    p *= __fdividef(1.0f, r);
                }
            }
#pragma unroll
            for (int k = 0; k < 8; k++) { cur[k] = nxt[k]; mcur[k] = mnxt[k]; }
        }
#pragma unroll
        for (int k = 0; k < 7; k++) {     // t = 505..511
            float w = __expf(cur[k]);
            float p0 = __shfl_sync(FULL, p, 0), p1 = __shfl_sync(FULL, p, 1);
            float p2 = __shfl_sync(FULL, p, 2), p3 = __shfl_sync(FULL, p, 3);
            float p4 = __shfl_sync(FULL, p, 4), p5 = __shfl_sync(FULL, p, 5);
            float p6 = __shfl_sync(FULL, p, 6), p7 = __shfl_sync(FULL, p, 7);
            float p8 = __shfl_sync(FULL, p, 8);
            float s01 = fmaf(p0, E[0], p1 * E[1]);
            float s23 = fmaf(p2, E[2], p3 * E[3]);
            float s45 = fmaf(p4, E[4], p5 * E[5]);
            float s67 = fmaf(p6, E[6], p7 * E[7]);
            float s = ((s01 + s23) + (s45 + s67)) + p8 * E[8];
            float pn = s * w;
            p = (mcur[k] > 0) ? pn : p;
        }

        float f = p * eend;
        float tot = 0.f;
#pragma unroll
        for (int i = 0; i < 9; i++) tot += __shfl_sync(FULL, f, i);
        if (lane == 0) g_logZ[b] = logacc + __logf(tot);

    } else if (blk < 128) {
        // ---------- Viterbi decode (bit-exact) + fast backtrace ----------
        int b = blk - 64;
        const float* emb = g_em + (long)b * S * L;
        float Tc[9];
#pragma unroll
        for (int i = 0; i < 9; i++) Tc[i] = trans[i * 9 + jj];
        float v = startT[jj] + emb[jj];

        float cur[8];
#pragma unroll
        for (int k = 0; k < 8; k++) cur[k] = emb[(1 + k) * 9 + jj];

        int tb = 1;
        for (; tb + 8 <= S; tb += 8) {
            float nxt[8];
#pragma unroll
            for (int k = 0; k < 8; k++) {
                int t2 = tb + 8 + k;
                nxt[k] = (t2 < S) ? emb[t2 * 9 + jj] : 0.f;
            }
#pragma unroll
            for (int k = 0; k < 8; k++) {
                float e = cur[k];
                float vi[9];
#pragma unroll
                for (int i = 0; i < 9; i++)
                    vi[i] = (__shfl_sync(FULL, v, i) + Tc[i]) + e;  // ref op order
                float a01 = fmaxf(vi[0], vi[1]);
                float a23 = fmaxf(vi[2], vi[3]);
                float a45 = fmaxf(vi[4], vi[5]);
                float a67 = fmaxf(vi[6], vi[7]);
                float M = fmaxf(fmaxf(fmaxf(a01, a23), fmaxf(a45, a67)), vi[8]);
                int arg = 8;                                        // first-occurrence
#pragma unroll
                for (int i = 7; i >= 0; i--) arg = (vi[i] == M) ? i : arg;
                if (lane < 9) bp[(tb + k - 1) * 9 + jj] = (unsigned char)arg;
                v = M;
            }
#pragma unroll
            for (int k = 0; k < 8; k++) cur[k] = nxt[k];
        }
#pragma unroll
        for (int k = 0; k < 7; k++) {                               // t = 505..511
            float e = cur[k];
            float vi[9];
#pragma unroll
            for (int i = 0; i < 9; i++)
                vi[i] = (__shfl_sync(FULL, v, i) + Tc[i]) + e;
            float a01 = fmaxf(vi[0], vi[1]);
            float a23 = fmaxf(vi[2], vi[3]);
            float a45 = fmaxf(vi[4], vi[5]);
            float a67 = fmaxf(vi[6], vi[7]);
            float M = fmaxf(fmaxf(fmaxf(a01, a23), fmaxf(a45, a67)), vi[8]);
            int arg = 8;
#pragma unroll
            for (int i = 7; i >= 0; i--) arg = (vi[i] == M) ? i : arg;
            if (lane < 9) bp[(tb + k - 1) * 9 + jj] = (unsigned char)arg;
            v = M;
        }
        __syncwarp();

        // final tag (all lanes compute identically)
        float fj = v + endT[jj];
        float fv[9];
#pragma unroll
        for (int i = 0; i < 9; i++) fv[i] = __shfl_sync(FULL, fj, i);
        float best = fv[0];
        int tag511 = 0;
#pragma unroll
        for (int i = 1; i < 9; i++)
            if (fv[i] > best) { best = fv[i]; tag511 = i; }   // first-max tie

        // build 2-step composed pointers C[t/2-1][j] = P(t-1)[P(t)[j]], even t
        for (int idx = lane; idx < 255 * 9; idx += 32) {
            int ci = idx / 9;
            int j = idx - ci * 9;
            int t = 2 * ci + 2;
            comp[idx] = bp[(t - 2) * 9 + bp[(t - 1) * 9 + j]];
        }
        __syncwarp();

        // chase even tags (lane 0): 255 dependent hops instead of 511
        if (lane == 0) {
            int cur_t = bp[510 * 9 + tag511];   // tag at t=510
            etag[255] = (unsigned char)cur_t;
            for (int t = 510; t >= 2; t -= 2) {
                cur_t = comp[((t - 2) >> 1) * 9 + cur_t];
                etag[(t - 2) >> 1] = (unsigned char)cur_t;
            }
        }
        __syncwarp();

        // fill odd tags + outputs + correct count (warp-parallel)
        const int* lb = label + b * S;
        float* pout = out + 2 + (long)b * S;
        float cnt = 0.f;
        for (int t = lane; t < S; t += 32) {
            int tg;
            if (t == 511) tg = tag511;
            else if ((t & 1) == 0) tg = etag[t >> 1];
            else tg = bp[t * 9 + etag[(t + 1) >> 1]];
            int lab = lb[t];
            int pv = (lab > 0) ? tg : 0;
            pout[t] = (float)pv;
            cnt += (pv == lab) ? 1.f : 0.f;
        }
#pragma unroll
        for (int o = 16; o > 0; o >>= 1) cnt += __shfl_xor_sync(FULL, cnt, o);
        if (lane == 0) g_corr[b] = cnt;

    } else {
        // ---------- gold path score (masked scan) + label copy ----------
        int b = blk - 128;
        const int* lb = label + b * S;
        const int* mb = mask + b * S;
        const float* emb = g_em + (long)b * S * L;
        int t0 = lane * 16;

        int ll = -1;
#pragma unroll
        for (int k = 0; k < 16; k++) {
            int t = t0 + k;
            if ((t == 0) | (mb[t] > 0)) ll = t;
        }
        int inc = ll;
#pragma unroll
        for (int o = 1; o < 32; o <<= 1) {
            int vv = __shfl_up_sync(FULL, inc, o);
            if (lane >= o) inc = max(inc, vv);
        }
        int exc = __shfl_up_sync(FULL, inc, 1);
        if (lane == 0) exc = -1;
        int lastAll = __shfl_sync(FULL, inc, 31);

        float sc = 0.f;
        int prevIdx = exc;
#pragma unroll
        for (int k = 0; k < 16; k++) {
            int t = t0 + k;
            int mt = mb[t];
            int tg = lb[t];
            if (t >= 1) {
                int pt = lb[prevIdx];
                float s = trans[pt * 9 + tg] + emb[t * 9 + tg];
                sc += s * (float)mt;
            }
            if ((t == 0) | (mt > 0)) prevIdx = t;
        }
#pragma unroll
        for (int o = 16; o > 0; o >>= 1) sc += __shfl_xor_sync(FULL, sc, o);

        if (lane == 0) {
            int tg0 = lb[0];
            g_score[b] = startT[tg0] + emb[tg0] + sc + endT[lb[lastAll]];
        }

        float* lout = out + 2 + (long)B * S;
        for (int t = lane; t < S; t += 32)
            lout[(long)b * S + t] = (float)lb[t];
    }

    // ---------- per-warp done accounting; last warp finalizes + resets ----------
    __threadfence();
    unsigned my = 0;
    if (lane == 0) my = atomicAdd(&g_done, 1u);
    my = __shfl_sync(FULL, my, 0);
    if (my == 191u) {
        float d = 0.f, c = 0.f;
#pragma unroll
        for (int k = lane; k < 64; k += 32) {
            d += __ldcg(&g_score[k]) - __ldcg(&g_logZ[k]);
            c += __ldcg(&g_corr[k]);
        }
#pragma unroll
        for (int o = 16; o > 0; o >>= 1) {
            d += __shfl_xor_sync(FULL, d, o);
            c += __shfl_xor_sync(FULL, c, o);
        }
        if (lane == 0) {
            out[0] = -d / (float)B;
            out[1] = c;
            g_done = 0;   // reset for next graph replay
        }
    }
}

// ---------------------------------------------------------------------------
extern "C" void kernel_launch(void* const* d_in, const int* in_sizes, int n_in,
                              void* d_out, int out_size) {
    const float* hidden = (const float*)d_in[0];
    const int*   label  = (const int*)d_in[1];
    const int*   mask   = (const int*)d_in[2];
    const float* W      = (const float*)d_in[3];
    const float* bias   = (const float*)d_in[4];
    const float* startT = (const float*)d_in[5];
    const float* endT   = (const float*)d_in[6];
    const float* trans  = (const float*)d_in[7];
    float* out = (float*)d_out;

    emis_kernel<<<2048, 256>>>(hidden, W, bias);
    crf_kernel<<<192, 32>>>(label, mask, startT, endT, trans, out);
}

// round 9
// speedup vs baseline: 1.1954x; 1.0325x over previous
#include <cuda_runtime.h>
#include <cuda_bf16.h>

#define FULL 0xffffffffu

static constexpr int B = 64;
static constexpr int S = 512;
static constexpr int H = 768;
static constexpr int L = 9;

__device__ float g_em[B * S * L];     // [b][t][j]
__device__ float g_score[B];
__device__ float g_logZ[B];
__device__ float g_corr[B];
__device__ unsigned g_done;           // finished crf warps (target 128)

// ---------------------------------------------------------------------------
// Kernel 1: emissions = hidden @ W + b   (unchanged from round 8, ~30 us)
// ---------------------------------------------------------------------------
__global__ void __launch_bounds__(256) emis_kernel(const float* __restrict__ hidden,
                                                   const float* __restrict__ W,
                                                   const float* __restrict__ bias) {
    __shared__ float sWT[L * H];  // [j][h], 27648 B
    for (int i = threadIdx.x; i < L * H; i += 256) {
        int j = i / H, h = i - j * H;
        sWT[i] = W[h * L + j];
    }
    __syncthreads();

    int warp = threadIdx.x >> 5;
    int lane = threadIdx.x & 31;
    long row0 = (long)(blockIdx.x * 8 + warp) * 2;
    const float* h0 = hidden + row0 * H;

    float acc0[9], acc1[9];
#pragma unroll
    for (int j = 0; j < 9; j++) { acc0[j] = 0.f; acc1[j] = 0.f; }

    float4 nx0 = *(const float4*)(h0 + lane * 4);
    float4 nx1 = *(const float4*)(h0 + H + lane * 4);

#pragma unroll
    for (int k = 0; k < 6; k++) {
        float4 x0 = nx0, x1 = nx1;
        if (k < 5) {
            int hb = (k + 1) * 128 + lane * 4;
            nx0 = *(const float4*)(h0 + hb);
            nx1 = *(const float4*)(h0 + H + hb);
        }
        int hb = k * 128 + lane * 4;
#pragma unroll
        for (int j = 0; j < 9; j++) {
            float4 w4 = *(const float4*)(sWT + j * H + hb);
            acc0[j] = fmaf(x0.x, w4.x, acc0[j]);
            acc0[j] = fmaf(x0.y, w4.y, acc0[j]);
            acc0[j] = fmaf(x0.z, w4.z, acc0[j]);
            acc0[j] = fmaf(x0.w, w4.w, acc0[j]);
            acc1[j] = fmaf(x1.x, w4.x, acc1[j]);
            acc1[j] = fmaf(x1.y, w4.y, acc1[j]);
            acc1[j] = fmaf(x1.z, w4.z, acc1[j]);
            acc1[j] = fmaf(x1.w, w4.w, acc1[j]);
        }
    }

#pragma unroll
    for (int j = 0; j < 9; j++) {
#pragma unroll
        for (int o = 16; o > 0; o >>= 1) {
            acc0[j] += __shfl_xor_sync(FULL, acc0[j], o);
            acc1[j] += __shfl_xor_sync(FULL, acc1[j], o);
        }
    }

    if (lane == 0) {
        float v[18];
#pragma unroll
        for (int j = 0; j < 9; j++) {
            float bb = bias[j];
            v[j] = acc0[j] + bb;
            v[9 + j] = acc1[j] + bb;
        }
        float2* dst = (float2*)(g_em + row0 * 9);
#pragma unroll
        for (int q = 0; q < 9; q++) dst[q] = make_float2(v[2 * q], v[2 * q + 1]);
    }
}

// ---------------------------------------------------------------------------
// Kernel 2: 128 blocks x 32 threads -> one chain warp per SM (wave-1 distinct)
//   blocks   0.. 63 : Viterbi + fast backtrace + predict + correct   [the wall]
//   blocks  64..127 : forward DP (logZ), then numerator scan + label copy
// Last finishing warp (of 128) computes loss/correct and resets g_done.
// ---------------------------------------------------------------------------
__global__ void __launch_bounds__(32)
crf_kernel(const int* __restrict__ label,
           const int* __restrict__ mask,
           const float* __restrict__ startT,
           const float* __restrict__ endT,
           const float* __restrict__ trans,
           float* __restrict__ out) {
    __shared__ unsigned char bp[(S - 1) * L];    // backpointers (4599 B)
    __shared__ unsigned char comp[255 * L];      // 2-step composed pointers
    __shared__ unsigned char etag[256];          // tags at even t

    int blk = blockIdx.x;
    int lane = threadIdx.x;
    int jj = lane % 9;

    if (blk < 64) {
        // ---------- Viterbi decode (bit-exact) + fast backtrace ----------
        int b = blk;
        const float* emb = g_em + (long)b * S * L;
        float Tc[9];
#pragma unroll
        for (int i = 0; i < 9; i++) Tc[i] = trans[i * 9 + jj];
        float v = startT[jj] + emb[jj];

        float cur[8];
#pragma unroll
        for (int k = 0; k < 8; k++) cur[k] = emb[(1 + k) * 9 + jj];

        int tb = 1;
        for (; tb + 8 <= S; tb += 8) {
            float nxt[8];
#pragma unroll
            for (int k = 0; k < 8; k++) {
                int t2 = tb + 8 + k;
                nxt[k] = (t2 < S) ? emb[t2 * 9 + jj] : 0.f;
            }
#pragma unroll
            for (int k = 0; k < 8; k++) {
                float e = cur[k];
                float vi[9];
#pragma unroll
                for (int i = 0; i < 9; i++)
                    vi[i] = (__shfl_sync(FULL, v, i) + Tc[i]) + e;  // ref op order
                float a01 = fmaxf(vi[0], vi[1]);
                float a23 = fmaxf(vi[2], vi[3]);
                float a45 = fmaxf(vi[4], vi[5]);
                float a67 = fmaxf(vi[6], vi[7]);
                float M = fmaxf(fmaxf(fmaxf(a01, a23), fmaxf(a45, a67)), vi[8]);
                int arg = 8;                                        // first-occurrence
#pragma unroll
                for (int i = 7; i >= 0; i--) arg = (vi[i] == M) ? i : arg;
                if (lane < 9) bp[(tb + k - 1) * 9 + jj] = (unsigned char)arg;
                v = M;
            }
#pragma unroll
            for (int k = 0; k < 8; k++) cur[k] = nxt[k];
        }
#pragma unroll
        for (int k = 0; k < 7; k++) {                               // t = 505..511
            float e = cur[k];
            float vi[9];
#pragma unroll
            for (int i = 0; i < 9; i++)
                vi[i] = (__shfl_sync(FULL, v, i) + Tc[i]) + e;
            float a01 = fmaxf(vi[0], vi[1]);
            float a23 = fmaxf(vi[2], vi[3]);
            float a45 = fmaxf(vi[4], vi[5]);
            float a67 = fmaxf(vi[6], vi[7]);
            float M = fmaxf(fmaxf(fmaxf(a01, a23), fmaxf(a45, a67)), vi[8]);
            int arg = 8;
#pragma unroll
            for (int i = 7; i >= 0; i--) arg = (vi[i] == M) ? i : arg;
            if (lane < 9) bp[(tb + k - 1) * 9 + jj] = (unsigned char)arg;
            v = M;
        }
        __syncwarp();

        float fj = v + endT[jj];
        float fv[9];
#pragma unroll
        for (int i = 0; i < 9; i++) fv[i] = __shfl_sync(FULL, fj, i);
        float best = fv[0];
        int tag511 = 0;
#pragma unroll
        for (int i = 1; i < 9; i++)
            if (fv[i] > best) { best = fv[i]; tag511 = i; }   // first-max tie

        // build 2-step composed pointers C[t/2-1][j] = P(t-1)[P(t)[j]], even t
        for (int idx = lane; idx < 255 * 9; idx += 32) {
            int ci = idx / 9;
            int j = idx - ci * 9;
            int t = 2 * ci + 2;
            comp[idx] = bp[(t - 2) * 9 + bp[(t - 1) * 9 + j]];
        }
        __syncwarp();

        if (lane == 0) {
            int cur_t = bp[510 * 9 + tag511];   // tag at t=510
            etag[255] = (unsigned char)cur_t;
            for (int t = 510; t >= 2; t -= 2) {
                cur_t = comp[((t - 2) >> 1) * 9 + cur_t];
                etag[(t - 2) >> 1] = (unsigned char)cur_t;
            }
        }
        __syncwarp();

        const int* lb = label + b * S;
        float* pout = out + 2 + (long)b * S;
        float cnt = 0.f;
        for (int t = lane; t < S; t += 32) {
            int tg;
            if (t == 511) tg = tag511;
            else if ((t & 1) == 0) tg = etag[t >> 1];
            else tg = bp[t * 9 + etag[(t + 1) >> 1]];
            int lab = lb[t];
            int pv = (lab > 0) ? tg : 0;
            pout[t] = (float)pv;
            cnt += (pv == lab) ? 1.f : 0.f;
        }
#pragma unroll
        for (int o = 16; o > 0; o >>= 1) cnt += __shfl_xor_sync(FULL, cnt, o);
        if (lane == 0) g_corr[b] = cnt;

    } else {
        // ---------- forward DP (logZ), then numerator + label copy ----------
        int b = blk - 64;
        const float* emb = g_em + (long)b * S * L;
        const int* mb = mask + b * S;
        float E[9];
#pragma unroll
        for (int i = 0; i < 9; i++) E[i] = __expf(trans[i * 9 + jj]);
        float eend = __expf(endT[jj]);

        float p = __expf(startT[jj] + emb[jj]);
        float logacc = 0.f;

        float cur[8]; int mcur[8];
#pragma unroll
        for (int k = 0; k < 8; k++) { cur[k] = emb[(1 + k) * 9 + jj]; mcur[k] = mb[1 + k]; }

        int tb = 1;
        for (; tb + 8 <= S; tb += 8) {
            float w[8];
#pragma unroll
            for (int k = 0; k < 8; k++) w[k] = __expf(cur[k]);
            float nxt[8]; int mnxt[8];
#pragma unroll
            for (int k = 0; k < 8; k++) {
                int t2 = tb + 8 + k;
                if (t2 < S) { nxt[k] = emb[t2 * 9 + jj]; mnxt[k] = mb[t2]; }
                else        { nxt[k] = 0.f;              mnxt[k] = 0; }
            }
#pragma unroll
            for (int k = 0; k < 8; k++) {
                float p0 = __shfl_sync(FULL, p, 0), p1 = __shfl_sync(FULL, p, 1);
                float p2 = __shfl_sync(FULL, p, 2), p3 = __shfl_sync(FULL, p, 3);
                float p4 = __shfl_sync(FULL, p, 4), p5 = __shfl_sync(FULL, p, 5);
                float p6 = __shfl_sync(FULL, p, 6), p7 = __shfl_sync(FULL, p, 7);
                float p8 = __shfl_sync(FULL, p, 8);
                float s01 = fmaf(p0, E[0], p1 * E[1]);
                float s23 = fmaf(p2, E[2], p3 * E[3]);
                float s45 = fmaf(p4, E[4], p5 * E[5]);
                float s67 = fmaf(p6, E[6], p7 * E[7]);
                float s = ((s01 + s23) + (s45 + s67)) + p8 * E[8];
                float pn = s * w[k];
                p = (mcur[k] > 0) ? pn : p;
                int t = tb + k;
                if ((t & 15) == 0) {
                    float r = __shfl_sync(FULL, p, 0);
                    logacc += __logf(r);
                    p *= __fdividef(1.0f, r);
                }
            }
#pragma unroll
            for (int k = 0; k < 8; k++) { cur[k] = nxt[k]; mcur[k] = mnxt[k]; }
        }
#pragma unroll
        for (int k = 0; k < 7; k++) {     // t = 505..511
            float w = __expf(cur[k]);
            float p0 = __shfl_sync(FULL, p, 0), p1 = __shfl_sync(FULL, p, 1);
            float p2 = __shfl_sync(FULL, p, 2), p3 = __shfl_sync(FULL, p, 3);
            float p4 = __shfl_sync(FULL, p, 4), p5 = __shfl_sync(FULL, p, 5);
            float p6 = __shfl_sync(FULL, p, 6), p7 = __shfl_sync(FULL, p, 7);
            float p8 = __shfl_sync(FULL, p, 8);
            float s01 = fmaf(p0, E[0], p1 * E[1]);
            float s23 = fmaf(p2, E[2], p3 * E[3]);
            float s45 = fmaf(p4, E[4], p5 * E[5]);
            float s67 = fmaf(p6, E[6], p7 * E[7]);
            float s = ((s01 + s23) + (s45 + s67)) + p8 * E[8];
            float pn = s * w;
            p = (mcur[k] > 0) ? pn : p;
        }

        float f = p * eend;
        float tot = 0.f;
#pragma unroll
        for (int i = 0; i < 9; i++) tot += __shfl_sync(FULL, f, i);
        if (lane == 0) g_logZ[b] = logacc + __logf(tot);

        // ---------- gold path score (masked scan) + label copy ----------
        const int* lb = label + b * S;
        int t0 = lane * 16;

        int ll = -1;
#pragma unroll
        for (int k = 0; k < 16; k++) {
            int t = t0 + k;
            if ((t == 0) | (mb[t] > 0)) ll = t;
        }
        int inc = ll;
#pragma unroll
        for (int o = 1; o < 32; o <<= 1) {
            int vv = __shfl_up_sync(FULL, inc, o);
            if (lane >= o) inc = max(inc, vv);
        }
        int exc = __shfl_up_sync(FULL, inc, 1);
        if (lane == 0) exc = -1;
        int lastAll = __shfl_sync(FULL, inc, 31);

        float sc = 0.f;
        int prevIdx = exc;
#pragma unroll
        for (int k = 0; k < 16; k++) {
            int t = t0 + k;
            int mt = mb[t];
            int tg = lb[t];
            if (t >= 1) {
                int pt = lb[prevIdx];
                float s = trans[pt * 9 + tg] + emb[t * 9 + tg];
                sc += s * (float)mt;
            }
            if ((t == 0) | (mt > 0)) prevIdx = t;
        }
#pragma unroll
        for (int o = 16; o > 0; o >>= 1) sc += __shfl_xor_sync(FULL, sc, o);

        if (lane == 0) {
            int tg0 = lb[0];
            g_score[b] = startT[tg0] + emb[tg0] + sc + endT[lb[lastAll]];
        }

        float* lout = out + 2 + (long)B * S;
        for (int t = lane; t < S; t += 32)
            lout[(long)b * S + t] = (float)lb[t];
    }

    // ---------- per-warp done accounting; last warp finalizes + resets ----------
    __threadfence();
    unsigned my = 0;
    if (lane == 0) my = atomicAdd(&g_done, 1u);
    my = __shfl_sync(FULL, my, 0);
    if (my == 127u) {
        float d = 0.f, c = 0.f;
#pragma unroll
        for (int k = lane; k < 64; k += 32) {
            d += __ldcg(&g_score[k]) - __ldcg(&g_logZ[k]);
            c += __ldcg(&g_corr[k]);
        }
#pragma unroll
        for (int o = 16; o > 0; o >>= 1) {
            d += __shfl_xor_sync(FULL, d, o);
            c += __shfl_xor_sync(FULL, c, o);
        }
        if (lane == 0) {
            out[0] = -d / (float)B;
            out[1] = c;
            g_done = 0;   // reset for next graph replay
        }
    }
}

// ---------------------------------------------------------------------------
extern "C" void kernel_launch(void* const* d_in, const int* in_sizes, int n_in,
                              void* d_out, int out_size) {
    const float* hidden = (const float*)d_in[0];
    const int*   label  = (const int*)d_in[1];
    const int*   mask   = (const int*)d_in[2];
    const float* W      = (const float*)d_in[3];
    const float* bias   = (const float*)d_in[4];
    const float* startT = (const float*)d_in[5];
    const float* endT   = (const float*)d_in[6];
    const float* trans  = (const float*)d_in[7];
    float* out = (float*)d_out;

    emis_kernel<<<2048, 256>>>(hidden, W, bias);
    crf_kernel<<<128, 32>>>(label, mask, startT, endT, trans, out);
}

// round 10
// speedup vs baseline: 1.2364x; 1.0343x over previous
#include <cuda_runtime.h>
#include <cuda_bf16.h>

#define FULL 0xffffffffu

static constexpr int B = 64;
static constexpr int S = 512;
static constexpr int H = 768;
static constexpr int L = 9;

__device__ float g_em[B * S * L];     // [b][t][j]
__device__ float g_score[B];
__device__ float g_logZ[B];
__device__ float g_corr[B];
__device__ unsigned g_done;           // finished crf warps (target 128)

// ---------------------------------------------------------------------------
// Kernel 1: emissions = hidden @ W + b
// block 256 (8 warps), 4 rows/warp, batched float4 loads (MLP=4); grid 1024
// ---------------------------------------------------------------------------
__global__ void __launch_bounds__(256) emis_kernel(const float* __restrict__ hidden,
                                                   const float* __restrict__ W,
                                                   const float* __restrict__ bias) {
    __shared__ float sWT[L * H];  // [j][h], 27648 B
    for (int i = threadIdx.x; i < L * H; i += 256) {
        int j = i / H, h = i - j * H;
        sWT[i] = W[h * L + j];
    }
    __syncthreads();

    int warp = threadIdx.x >> 5;
    int lane = threadIdx.x & 31;
    long row0 = (long)(blockIdx.x * 8 + warp) * 4;
    const float* h0 = hidden + row0 * H;

    float acc[4][9];
#pragma unroll
    for (int r = 0; r < 4; r++)
#pragma unroll
        for (int j = 0; j < 9; j++) acc[r][j] = 0.f;

#pragma unroll
    for (int k = 0; k < 6; k++) {
        int hb = k * 128 + lane * 4;
        float4 x0 = *(const float4*)(h0 + hb);
        float4 x1 = *(const float4*)(h0 + H + hb);
        float4 x2 = *(const float4*)(h0 + 2 * H + hb);
        float4 x3 = *(const float4*)(h0 + 3 * H + hb);
#pragma unroll
        for (int j = 0; j < 9; j++) {
            float4 w4 = *(const float4*)(sWT + j * H + hb);
            acc[0][j] = fmaf(x0.x, w4.x, acc[0][j]);
            acc[0][j] = fmaf(x0.y, w4.y, acc[0][j]);
            acc[0][j] = fmaf(x0.z, w4.z, acc[0][j]);
            acc[0][j] = fmaf(x0.w, w4.w, acc[0][j]);
            acc[1][j] = fmaf(x1.x, w4.x, acc[1][j]);
            acc[1][j] = fmaf(x1.y, w4.y, acc[1][j]);
            acc[1][j] = fmaf(x1.z, w4.z, acc[1][j]);
            acc[1][j] = fmaf(x1.w, w4.w, acc[1][j]);
            acc[2][j] = fmaf(x2.x, w4.x, acc[2][j]);
            acc[2][j] = fmaf(x2.y, w4.y, acc[2][j]);
            acc[2][j] = fmaf(x2.z, w4.z, acc[2][j]);
            acc[2][j] = fmaf(x2.w, w4.w, acc[2][j]);
            acc[3][j] = fmaf(x3.x, w4.x, acc[3][j]);
            acc[3][j] = fmaf(x3.y, w4.y, acc[3][j]);
            acc[3][j] = fmaf(x3.z, w4.z, acc[3][j]);
            acc[3][j] = fmaf(x3.w, w4.w, acc[3][j]);
        }
    }

#pragma unroll
    for (int r = 0; r < 4; r++)
#pragma unroll
        for (int j = 0; j < 9; j++) {
#pragma unroll
            for (int o = 16; o > 0; o >>= 1)
                acc[r][j] += __shfl_xor_sync(FULL, acc[r][j], o);
        }

    if (lane == 0) {
        float v[36];
#pragma unroll
        for (int r = 0; r < 4; r++)
#pragma unroll
            for (int j = 0; j < 9; j++) v[r * 9 + j] = acc[r][j] + bias[j];
        float4* dst = (float4*)(g_em + row0 * 9);  // row0 mult of 4 -> 144B aligned
#pragma unroll
        for (int q = 0; q < 9; q++)
            dst[q] = make_float4(v[4 * q], v[4 * q + 1], v[4 * q + 2], v[4 * q + 3]);
    }
}

// ---------------------------------------------------------------------------
// Kernel 2: 128 blocks x 32 threads, one chain warp per SM.
// Exchange via double-buffered smem broadcast (STS + syncwarp + LDS.128)
// instead of 9x SHFL.IDX per step. Values bit-identical.
//   blocks   0.. 63 : Viterbi + fast backtrace + predict + correct
//   blocks  64..127 : forward DP (logZ), then numerator scan + label copy
// ---------------------------------------------------------------------------
__global__ void __launch_bounds__(32)
crf_kernel(const int* __restrict__ label,
           const int* __restrict__ mask,
           const float* __restrict__ startT,
           const float* __restrict__ endT,
           const float* __restrict__ trans,
           float* __restrict__ out) {
    __shared__ __align__(16) float sx[2][12];    // double-buffered exchange slots
    __shared__ unsigned char bp[(S - 1) * L];    // backpointers (4599 B)
    __shared__ unsigned char comp[255 * L];      // 2-step composed pointers
    __shared__ unsigned char etag[256];          // tags at even t

    int blk = blockIdx.x;
    int lane = threadIdx.x;
    int jj = lane % 9;

    if (blk < 64) {
        // ---------- Viterbi decode (bit-exact) + fast backtrace ----------
        int b = blk;
        const float* emb = g_em + (long)b * S * L;
        float Tc[9];
#pragma unroll
        for (int i = 0; i < 9; i++) Tc[i] = trans[i * 9 + jj];
        float v = startT[jj] + emb[jj];

        float cur[8];
#pragma unroll
        for (int k = 0; k < 8; k++) cur[k] = emb[(1 + k) * 9 + jj];

        int tb = 1;
        for (; tb + 8 <= S; tb += 8) {
            float nxt[8];
#pragma unroll
            for (int k = 0; k < 8; k++) {
                int t2 = tb + 8 + k;
                nxt[k] = (t2 < S) ? emb[t2 * 9 + jj] : 0.f;
            }
#pragma unroll
            for (int k = 0; k < 8; k++) {
                int t = tb + k;
                float e = cur[k];
                float* sb = &sx[t & 1][0];
                if (lane < 9) sb[jj] = v;
                __syncwarp();
                float4 a0 = *(const float4*)(sb);
                float4 a1 = *(const float4*)(sb + 4);
                float v8 = sb[8];
                float vi[9];
                vi[0] = (a0.x + Tc[0]) + e;   // ref op order
                vi[1] = (a0.y + Tc[1]) + e;
                vi[2] = (a0.z + Tc[2]) + e;
                vi[3] = (a0.w + Tc[3]) + e;
                vi[4] = (a1.x + Tc[4]) + e;
                vi[5] = (a1.y + Tc[5]) + e;
                vi[6] = (a1.z + Tc[6]) + e;
                vi[7] = (a1.w + Tc[7]) + e;
                vi[8] = (v8 + Tc[8]) + e;
                float a01 = fmaxf(vi[0], vi[1]);
                float a23 = fmaxf(vi[2], vi[3]);
                float a45 = fmaxf(vi[4], vi[5]);
                float a67 = fmaxf(vi[6], vi[7]);
                float M = fmaxf(fmaxf(fmaxf(a01, a23), fmaxf(a45, a67)), vi[8]);
                int arg = 8;                                        // first-occurrence
#pragma unroll
                for (int i = 7; i >= 0; i--) arg = (vi[i] == M) ? i : arg;
                if (lane < 9) bp[(t - 1) * 9 + jj] = (unsigned char)arg;
                v = M;
            }
#pragma unroll
            for (int k = 0; k < 8; k++) cur[k] = nxt[k];
        }
#pragma unroll
        for (int k = 0; k < 7; k++) {                               // t = 505..511
            int t = tb + k;
            float e = cur[k];
            float* sb = &sx[t & 1][0];
            if (lane < 9) sb[jj] = v;
            __syncwarp();
            float4 a0 = *(const float4*)(sb);
            float4 a1 = *(const float4*)(sb + 4);
            float v8 = sb[8];
            float vi[9];
            vi[0] = (a0.x + Tc[0]) + e;
            vi[1] = (a0.y + Tc[1]) + e;
            vi[2] = (a0.z + Tc[2]) + e;
            vi[3] = (a0.w + Tc[3]) + e;
            vi[4] = (a1.x + Tc[4]) + e;
            vi[5] = (a1.y + Tc[5]) + e;
            vi[6] = (a1.z + Tc[6]) + e;
            vi[7] = (a1.w + Tc[7]) + e;
            vi[8] = (v8 + Tc[8]) + e;
            float a01 = fmaxf(vi[0], vi[1]);
            float a23 = fmaxf(vi[2], vi[3]);
            float a45 = fmaxf(vi[4], vi[5]);
            float a67 = fmaxf(vi[6], vi[7]);
            float M = fmaxf(fmaxf(fmaxf(a01, a23), fmaxf(a45, a67)), vi[8]);
            int arg = 8;
#pragma unroll
            for (int i = 7; i >= 0; i--) arg = (vi[i] == M) ? i : arg;
            if (lane < 9) bp[(t - 1) * 9 + jj] = (unsigned char)arg;
            v = M;
        }
        __syncwarp();

        float fj = v + endT[jj];
        float fv[9];
#pragma unroll
        for (int i = 0; i < 9; i++) fv[i] = __shfl_sync(FULL, fj, i);
        float best = fv[0];
        int tag511 = 0;
#pragma unroll
        for (int i = 1; i < 9; i++)
            if (fv[i] > best) { best = fv[i]; tag511 = i; }   // first-max tie

        // build 2-step composed pointers C[t/2-1][j] = P(t-1)[P(t)[j]], even t
        for (int idx = lane; idx < 255 * 9; idx += 32) {
            int ci = idx / 9;
            int j = idx - ci * 9;
            int t = 2 * ci + 2;
            comp[idx] = bp[(t - 2) * 9 + bp[(t - 1) * 9 + j]];
        }
        __syncwarp();

        if (lane == 0) {
            int cur_t = bp[510 * 9 + tag511];   // tag at t=510
            etag[255] = (unsigned char)cur_t;
            for (int t = 510; t >= 2; t -= 2) {
                cur_t = comp[((t - 2) >> 1) * 9 + cur_t];
                etag[(t - 2) >> 1] = (unsigned char)cur_t;
            }
        }
        __syncwarp();

        const int* lb = label + b * S;
        float* pout = out + 2 + (long)b * S;
        float cnt = 0.f;
        for (int t = lane; t < S; t += 32) {
            int tg;
            if (t == 511) tg = tag511;
            else if ((t & 1) == 0) tg = etag[t >> 1];
            else tg = bp[t * 9 + etag[(t + 1) >> 1]];
            int lab = lb[t];
            int pv = (lab > 0) ? tg : 0;
            pout[t] = (float)pv;
            cnt += (pv == lab) ? 1.f : 0.f;
        }
#pragma unroll
        for (int o = 16; o > 0; o >>= 1) cnt += __shfl_xor_sync(FULL, cnt, o);
        if (lane == 0) g_corr[b] = cnt;

    } else {
        // ---------- forward DP (logZ), then numerator + label copy ----------
        int b = blk - 64;
        const float* emb = g_em + (long)b * S * L;
        const int* mb = mask + b * S;
        float E[9];
#pragma unroll
        for (int i = 0; i < 9; i++) E[i] = __expf(trans[i * 9 + jj]);
        float eend = __expf(endT[jj]);

        float p = __expf(startT[jj] + emb[jj]);
        float logacc = 0.f;

        float cur[8]; int mcur[8];
#pragma unroll
        for (int k = 0; k < 8; k++) { cur[k] = emb[(1 + k) * 9 + jj]; mcur[k] = mb[1 + k]; }

        int tb = 1;
        for (; tb + 8 <= S; tb += 8) {
            float w[8];
#pragma unroll
            for (int k = 0; k < 8; k++) w[k] = __expf(cur[k]);
            float nxt[8]; int mnxt[8];
#pragma unroll
            for (int k = 0; k < 8; k++) {
                int t2 = tb + 8 + k;
                if (t2 < S) { nxt[k] = emb[t2 * 9 + jj]; mnxt[k] = mb[t2]; }
                else        { nxt[k] = 0.f;              mnxt[k] = 0; }
            }
#pragma unroll
            for (int k = 0; k < 8; k++) {
                int t = tb + k;
                float* sb = &sx[t & 1][0];
                if (lane < 9) sb[jj] = p;
                __syncwarp();
                float4 a0 = *(const float4*)(sb);
                float4 a1 = *(const float4*)(sb + 4);
                float p8 = sb[8];
                float s01 = fmaf(a0.x, E[0], a0.y * E[1]);
                float s23 = fmaf(a0.z, E[2], a0.w * E[3]);
                float s45 = fmaf(a1.x, E[4], a1.y * E[5]);
                float s67 = fmaf(a1.z, E[6], a1.w * E[7]);
                float s = ((s01 + s23) + (s45 + s67)) + p8 * E[8];
                float pn = s * w[k];
                p = (mcur[k] > 0) ? pn : p;
                if ((t & 15) == 0) {
                    float r = __shfl_sync(FULL, p, 0);
                    logacc += __logf(r);
                    p *= __fdividef(1.0f, r);
                }
            }
#pragma unroll
            for (int k = 0; k < 8; k++) { cur[k] = nxt[k]; mcur[k] = mnxt[k]; }
        }
#pragma unroll
        for (int k = 0; k < 7; k++) {     // t = 505..511
            int t = tb + k;
            float w = __expf(cur[k]);
            float* sb = &sx[t & 1][0];
            if (lane < 9) sb[jj] = p;
            __syncwarp();
            float4 a0 = *(const float4*)(sb);
            float4 a1 = *(const float4*)(sb + 4);
            float p8 = sb[8];
            float s01 = fmaf(a0.x, E[0], a0.y * E[1]);
            float s23 = fmaf(a0.z, E[2], a0.w * E[3]);
            float s45 = fmaf(a1.x, E[4], a1.y * E[5]);
            float s67 = fmaf(a1.z, E[6], a1.w * E[7]);
            float s = ((s01 + s23) + (s45 + s67)) + p8 * E[8];
            float pn = s * w;
            p = (mcur[k] > 0) ? pn : p;
        }

        float f = p * eend;
        float tot = 0.f;
#pragma unroll
        for (int i = 0; i < 9; i++) tot += __shfl_sync(FULL, f, i);
        if (lane == 0) g_logZ[b] = logacc + __logf(tot);

        // ---------- gold path score (masked scan) + label copy ----------
        const int* lb = label + b * S;
        int t0 = lane * 16;

        int ll = -1;
#pragma unroll
        for (int k = 0; k < 16; k++) {
            int t = t0 + k;
            if ((t == 0) | (mb[t] > 0)) ll = t;
        }
        int inc = ll;
#pragma unroll
        for (int o = 1; o < 32; o <<= 1) {
            int vv = __shfl_up_sync(FULL, inc, o);
            if (lane >= o) inc = max(inc, vv);
        }
        int exc = __shfl_up_sync(FULL, inc, 1);
        if (lane == 0) exc = -1;
        int lastAll = __shfl_sync(FULL, inc, 31);

        float sc = 0.f;
        int prevIdx = exc;
#pragma unroll
        for (int k = 0; k < 16; k++) {
            int t = t0 + k;
            int mt = mb[t];
            int tg = lb[t];
            if (t >= 1) {
                int pt = lb[prevIdx];
                float s = trans[pt * 9 + tg] + emb[t * 9 + tg];
                sc += s * (float)mt;
            }
            if ((t == 0) | (mt > 0)) prevIdx = t;
        }
#pragma unroll
        for (int o = 16; o > 0; o >>= 1) sc += __shfl_xor_sync(FULL, sc, o);

        if (lane == 0) {
            int tg0 = lb[0];
            g_score[b] = startT[tg0] + emb[tg0] + sc + endT[lb[lastAll]];
        }

        float* lout = out + 2 + (long)B * S;
        for (int t = lane; t < S; t += 32)
            lout[(long)b * S + t] = (float)lb[t];
    }

    // ---------- per-warp done accounting; last warp finalizes + resets ----------
    __threadfence();
    unsigned my = 0;
    if (lane == 0) my = atomicAdd(&g_done, 1u);
    my = __shfl_sync(FULL, my, 0);
    if (my == 127u) {
        float d = 0.f, c = 0.f;
#pragma unroll
        for (int k = lane; k < 64; k += 32) {
            d += __ldcg(&g_score[k]) - __ldcg(&g_logZ[k]);
            c += __ldcg(&g_corr[k]);
        }
#pragma unroll
        for (int o = 16; o > 0; o >>= 1) {
            d += __shfl_xor_sync(FULL, d, o);
            c += __shfl_xor_sync(FULL, c, o);
        }
        if (lane == 0) {
            out[0] = -d / (float)B;
            out[1] = c;
            g_done = 0;   // reset for next graph replay
        }
    }
}

// ---------------------------------------------------------------------------
extern "C" void kernel_launch(void* const* d_in, const int* in_sizes, int n_in,
                              void* d_out, int out_size) {
    const float* hidden = (const float*)d_in[0];
    const int*   label  = (const int*)d_in[1];
    const int*   mask   = (const int*)d_in[2];
    const float* W      = (const float*)d_in[3];
    const float* bias   = (const float*)d_in[4];
    const float* startT = (const float*)d_in[5];
    const float* endT   = (const float*)d_in[6];
    const float* trans  = (const float*)d_in[7];
    float* out = (float*)d_out;

    emis_kernel<<<1024, 256>>>(hidden, W, bias);
    crf_kernel<<<128, 32>>>(label, mask, startT, endT, trans, out);
}

// round 11
// speedup vs baseline: 1.3654x; 1.1043x over previous
#include <cuda_runtime.h>
#include <cuda_bf16.h>

#define FULL 0xffffffffu

static constexpr int B = 64;
static constexpr int S = 512;
static constexpr int H = 768;
static constexpr int L = 9;
static constexpr int VROW = 12;   // floats per vbuf row (16B-aligned float4 reads)

__device__ float g_em[B * S * L];     // [b][t][j]
__device__ float g_score[B];
__device__ float g_logZ[B];
__device__ float g_corr[B];
__device__ unsigned g_done;           // finished crf blocks (target 128)

// ---------------------------------------------------------------------------
// Kernel 1: emissions = hidden @ W + b   (unchanged from round 10)
// ---------------------------------------------------------------------------
__global__ void __launch_bounds__(256) emis_kernel(const float* __restrict__ hidden,
                                                   const float* __restrict__ W,
                                                   const float* __restrict__ bias) {
    __shared__ float sWT[L * H];  // [j][h], 27648 B
    for (int i = threadIdx.x; i < L * H; i += 256) {
        int j = i / H, h = i - j * H;
        sWT[i] = W[h * L + j];
    }
    __syncthreads();

    int warp = threadIdx.x >> 5;
    int lane = threadIdx.x & 31;
    long row0 = (long)(blockIdx.x * 8 + warp) * 4;
    const float* h0 = hidden + row0 * H;

    float acc[4][9];
#pragma unroll
    for (int r = 0; r < 4; r++)
#pragma unroll
        for (int j = 0; j < 9; j++) acc[r][j] = 0.f;

#pragma unroll
    for (int k = 0; k < 6; k++) {
        int hb = k * 128 + lane * 4;
        float4 x0 = *(const float4*)(h0 + hb);
        float4 x1 = *(const float4*)(h0 + H + hb);
        float4 x2 = *(const float4*)(h0 + 2 * H + hb);
        float4 x3 = *(const float4*)(h0 + 3 * H + hb);
#pragma unroll
        for (int j = 0; j < 9; j++) {
            float4 w4 = *(const float4*)(sWT + j * H + hb);
            acc[0][j] = fmaf(x0.x, w4.x, acc[0][j]);
            acc[0][j] = fmaf(x0.y, w4.y, acc[0][j]);
            acc[0][j] = fmaf(x0.z, w4.z, acc[0][j]);
            acc[0][j] = fmaf(x0.w, w4.w, acc[0][j]);
            acc[1][j] = fmaf(x1.x, w4.x, acc[1][j]);
            acc[1][j] = fmaf(x1.y, w4.y, acc[1][j]);
            acc[1][j] = fmaf(x1.z, w4.z, acc[1][j]);
            acc[1][j] = fmaf(x1.w, w4.w, acc[1][j]);
            acc[2][j] = fmaf(x2.x, w4.x, acc[2][j]);
            acc[2][j] = fmaf(x2.y, w4.y, acc[2][j]);
            acc[2][j] = fmaf(x2.z, w4.z, acc[2][j]);
            acc[2][j] = fmaf(x2.w, w4.w, acc[2][j]);
            acc[3][j] = fmaf(x3.x, w4.x, acc[3][j]);
            acc[3][j] = fmaf(x3.y, w4.y, acc[3][j]);
            acc[3][j] = fmaf(x3.z, w4.z, acc[3][j]);
            acc[3][j] = fmaf(x3.w, w4.w, acc[3][j]);
        }
    }

#pragma unroll
    for (int r = 0; r < 4; r++)
#pragma unroll
        for (int j = 0; j < 9; j++) {
#pragma unroll
            for (int o = 16; o > 0; o >>= 1)
                acc[r][j] += __shfl_xor_sync(FULL, acc[r][j], o);
        }

    if (lane == 0) {
        float v[36];
#pragma unroll
        for (int r = 0; r < 4; r++)
#pragma unroll
            for (int j = 0; j < 9; j++) v[r * 9 + j] = acc[r][j] + bias[j];
        float4* dst = (float4*)(g_em + row0 * 9);  // row0 mult of 4 -> 144B aligned
#pragma unroll
        for (int q = 0; q < 9; q++)
            dst[q] = make_float4(v[4 * q], v[4 * q + 1], v[4 * q + 2], v[4 * q + 3]);
    }
}

// ---------------------------------------------------------------------------
// Kernel 2: 128 blocks x 64 threads.
//   blocks   0.. 63 : warp0 = Viterbi value chain (no argmax!) storing state
//                     trajectory to smem; warp1 = trailing bp/argmax pass;
//                     then warp0 backtrace + predict + correct.
//   blocks  64..127 : warp0 = forward DP (logZ) + numerator + label copy
//                     (bit-identical to round 10); warp1 idles.
// Last finishing block finalizes loss/correct and resets g_done.
// ---------------------------------------------------------------------------
__global__ void __launch_bounds__(64)
crf_kernel(const int* __restrict__ label,
           const int* __restrict__ mask,
           const float* __restrict__ startT,
           const float* __restrict__ endT,
           const float* __restrict__ trans,
           float* __restrict__ out) {
    __shared__ __align__(16) float vbuf[(S - 1) * VROW]; // v(t-1) rows, 24528 B
    __shared__ __align__(16) float sx[2][12];            // fwd exchange slots
    __shared__ unsigned char bp[(S - 1) * L];            // backpointers
    __shared__ unsigned char comp[255 * L];              // 2-step composed ptrs
    __shared__ unsigned char etag[256];                  // tags at even t
    __shared__ int prog;                                 // forward progress (t)

    int blk = blockIdx.x;
    int tid = threadIdx.x;
    int warp = tid >> 5;
    int lane = tid & 31;
    int jj = lane % 9;

    if (tid == 0) prog = 0;
    __syncthreads();   // barrier #1 (all threads, both block kinds)

    if (blk < 64) {
        int b = blk;
        const float* emb = g_em + (long)b * S * L;

        if (warp == 0) {
            // ===== Viterbi value chain: minimal per-step work =====
            float Tc[9];
#pragma unroll
            for (int i = 0; i < 9; i++) Tc[i] = trans[i * 9 + jj];
            float v = startT[jj] + emb[jj];

            float cur[8];
#pragma unroll
            for (int k = 0; k < 8; k++) cur[k] = emb[(1 + k) * 9 + jj];

            int tb = 1;
            for (; tb + 8 <= S; tb += 8) {
                float nxt[8];
#pragma unroll
                for (int k = 0; k < 8; k++) {
                    int t2 = tb + 8 + k;
                    nxt[k] = (t2 < S) ? emb[t2 * 9 + jj] : 0.f;
                }
#pragma unroll
                for (int k = 0; k < 8; k++) {
                    int t = tb + k;
                    float e = cur[k];
                    float* vb = &vbuf[(t - 1) * VROW];
                    if (lane < 9) vb[jj] = v;       // exchange == trajectory store
                    __syncwarp();
                    float4 a0 = *(const float4*)(vb);
                    float4 a1 = *(const float4*)(vb + 4);
                    float v8 = vb[8];
                    float u0 = a0.x + Tc[0];
                    float u1 = a0.y + Tc[1];
                    float u2 = a0.z + Tc[2];
                    float u3 = a0.w + Tc[3];
                    float u4 = a1.x + Tc[4];
                    float u5 = a1.y + Tc[5];
                    float u6 = a1.z + Tc[6];
                    float u7 = a1.w + Tc[7];
                    float u8 = v8 + Tc[8];
                    float b01 = fmaxf(u0, u1);
                    float b23 = fmaxf(u2, u3);
                    float b45 = fmaxf(u4, u5);
                    float b67 = fmaxf(u6, u7);
                    float U = fmaxf(fmaxf(fmaxf(b01, b23), fmaxf(b45, b67)), u8);
                    v = U + e;   // == max_i((v_i+T_ij)+e) by rounding monotonicity
                }
#pragma unroll
                for (int k = 0; k < 8; k++) cur[k] = nxt[k];
                if (lane == 0) { __threadfence_block(); *(volatile int*)&prog = tb + 7; }
            }
#pragma unroll
            for (int k = 0; k < 7; k++) {                 // t = 505..511
                int t = tb + k;
                float e = cur[k];
                float* vb = &vbuf[(t - 1) * VROW];
                if (lane < 9) vb[jj] = v;
                __syncwarp();
                float4 a0 = *(const float4*)(vb);
                float4 a1 = *(const float4*)(vb + 4);
                float v8 = vb[8];
                float u0 = a0.x + Tc[0];
                float u1 = a0.y + Tc[1];
                float u2 = a0.z + Tc[2];
                float u3 = a0.w + Tc[3];
                float u4 = a1.x + Tc[4];
                float u5 = a1.y + Tc[5];
                float u6 = a1.z + Tc[6];
                float u7 = a1.w + Tc[7];
                float u8 = v8 + Tc[8];
                float b01 = fmaxf(u0, u1);
                float b23 = fmaxf(u2, u3);
                float b45 = fmaxf(u4, u5);
                float b67 = fmaxf(u6, u7);
                float U = fmaxf(fmaxf(fmaxf(b01, b23), fmaxf(b45, b67)), u8);
                v = U + e;
            }
            if (lane == 0) { __threadfence_block(); *(volatile int*)&prog = S - 1; }
            __syncwarp();

            // final tag (all lanes compute identically)
            float fj = v + endT[jj];
            float fv[9];
#pragma unroll
            for (int i = 0; i < 9; i++) fv[i] = __shfl_sync(FULL, fj, i);
            float best = fv[0];
            int tag511 = 0;
#pragma unroll
            for (int i = 1; i < 9; i++)
                if (fv[i] > best) { best = fv[i]; tag511 = i; }   // first-max tie

            __syncthreads();   // barrier #2: join warp1's bp table

            // build 2-step composed pointers, even t in [2,510]
            for (int idx = lane; idx < 255 * 9; idx += 32) {
                int ci = idx / 9;
                int j = idx - ci * 9;
                int t = 2 * ci + 2;
                comp[idx] = bp[(t - 2) * 9 + bp[(t - 1) * 9 + j]];
            }
            __syncwarp();

            if (lane == 0) {
                int cur_t = bp[510 * 9 + tag511];   // tag at t=510
                etag[255] = (unsigned char)cur_t;
                for (int t = 510; t >= 2; t -= 2) {
                    cur_t = comp[((t - 2) >> 1) * 9 + cur_t];
                    etag[(t - 2) >> 1] = (unsigned char)cur_t;
                }
            }
            __syncwarp();

            const int* lb = label + b * S;
            float* pout = out + 2 + (long)b * S;
            float cnt = 0.f;
            for (int t = lane; t < S; t += 32) {
                int tg;
                if (t == 511) tg = tag511;
                else if ((t & 1) == 0) tg = etag[t >> 1];
                else tg = bp[t * 9 + etag[(t + 1) >> 1]];
                int lab = lb[t];
                int pv = (lab > 0) ? tg : 0;
                pout[t] = (float)pv;
                cnt += (pv == lab) ? 1.f : 0.f;
            }
#pragma unroll
            for (int o = 16; o > 0; o >>= 1) cnt += __shfl_xor_sync(FULL, cnt, o);
            if (lane == 0) g_corr[b] = cnt;

        } else {
            // ===== trailing bp/argmax pass (bit-identical to inline form) =====
            float Tc[9];
#pragma unroll
            for (int i = 0; i < 9; i++) Tc[i] = trans[i * 9 + jj];
            int g = lane / 9;                 // group 0..2 (lanes 27..31 idle)
            bool act = (lane < 27);

            for (int tc = 1; tc <= S - 1; tc += 3) {
                int t = tc + g;
                int need = tc + 2 < S - 1 ? tc + 2 : S - 1;
                while (*(volatile int*)&prog < need) __nanosleep(64);
                if (act && t <= S - 1) {
                    const float* vb = &vbuf[(t - 1) * VROW];
                    float4 a0 = *(const float4*)(vb);
                    float4 a1 = *(const float4*)(vb + 4);
                    float v8 = vb[8];
                    float e = emb[t * 9 + jj];
                    float vi[9];
                    vi[0] = (a0.x + Tc[0]) + e;   // ref op order
                    vi[1] = (a0.y + Tc[1]) + e;
                    vi[2] = (a0.z + Tc[2]) + e;
                    vi[3] = (a0.w + Tc[3]) + e;
                    vi[4] = (a1.x + Tc[4]) + e;
                    vi[5] = (a1.y + Tc[5]) + e;
                    vi[6] = (a1.z + Tc[6]) + e;
                    vi[7] = (a1.w + Tc[7]) + e;
                    vi[8] = (v8 + Tc[8]) + e;
                    float a01 = fmaxf(vi[0], vi[1]);
                    float a23 = fmaxf(vi[2], vi[3]);
                    float a45 = fmaxf(vi[4], vi[5]);
                    float a67 = fmaxf(vi[6], vi[7]);
                    float M = fmaxf(fmaxf(fmaxf(a01, a23), fmaxf(a45, a67)), vi[8]);
                    int arg = 8;                  // first-occurrence
#pragma unroll
                    for (int i = 7; i >= 0; i--) arg = (vi[i] == M) ? i : arg;
                    bp[(t - 1) * 9 + jj] = (unsigned char)arg;
                }
            }
            __syncthreads();   // barrier #2
            return;            // bp consumed by warp0 after the barrier
        }

    } else {
        if (warp == 1) { __syncthreads(); return; }   // barrier #2
        // ---------- forward DP (logZ), then numerator + label copy ----------
        int b = blk - 64;
        const float* emb = g_em + (long)b * S * L;
        const int* mb = mask + b * S;
        float E[9];
#pragma unroll
        for (int i = 0; i < 9; i++) E[i] = __expf(trans[i * 9 + jj]);
        float eend = __expf(endT[jj]);

        float p = __expf(startT[jj] + emb[jj]);
        float logacc = 0.f;

        float cur[8]; int mcur[8];
#pragma unroll
        for (int k = 0; k < 8; k++) { cur[k] = emb[(1 + k) * 9 + jj]; mcur[k] = mb[1 + k]; }

        int tb = 1;
        for (; tb + 8 <= S; tb += 8) {
            float w[8];
#pragma unroll
            for (int k = 0; k < 8; k++) w[k] = __expf(cur[k]);
            float nxt[8]; int mnxt[8];
#pragma unroll
            for (int k = 0; k < 8; k++) {
                int t2 = tb + 8 + k;
                if (t2 < S) { nxt[k] = emb[t2 * 9 + jj]; mnxt[k] = mb[t2]; }
                else        { nxt[k] = 0.f;              mnxt[k] = 0; }
            }
#pragma unroll
            for (int k = 0; k < 8; k++) {
                int t = tb + k;
                float* sb = &sx[t & 1][0];
                if (lane < 9) sb[jj] = p;
                __syncwarp();
                float4 a0 = *(const float4*)(sb);
                float4 a1 = *(const float4*)(sb + 4);
                float p8 = sb[8];
                float s01 = fmaf(a0.x, E[0], a0.y * E[1]);
                float s23 = fmaf(a0.z, E[2], a0.w * E[3]);
                float s45 = fmaf(a1.x, E[4], a1.y * E[5]);
                float s67 = fmaf(a1.z, E[6], a1.w * E[7]);
                float s = ((s01 + s23) + (s45 + s67)) + p8 * E[8];
                float pn = s * w[k];
                p = (mcur[k] > 0) ? pn : p;
                if ((t & 15) == 0) {
                    float r = __shfl_sync(FULL, p, 0);
                    logacc += __logf(r);
                    p *= __fdividef(1.0f, r);
                }
            }
#pragma unroll
            for (int k = 0; k < 8; k++) { cur[k] = nxt[k]; mcur[k] = mnxt[k]; }
        }
#pragma unroll
        for (int k = 0; k < 7; k++) {     // t = 505..511
            int t = tb + k;
            float w = __expf(cur[k]);
            float* sb = &sx[t & 1][0];
            if (lane < 9) sb[jj] = p;
            __syncwarp();
            float4 a0 = *(const float4*)(sb);
            float4 a1 = *(const float4*)(sb + 4);
            float p8 = sb[8];
            float s01 = fmaf(a0.x, E[0], a0.y * E[1]);
            float s23 = fmaf(a0.z, E[2], a0.w * E[3]);
            float s45 = fmaf(a1.x, E[4], a1.y * E[5]);
            float s67 = fmaf(a1.z, E[6], a1.w * E[7]);
            float s = ((s01 + s23) + (s45 + s67)) + p8 * E[8];
            float pn = s * w;
            p = (mcur[k] > 0) ? pn : p;
        }

        float f = p * eend;
        float tot = 0.f;
#pragma unroll
        for (int i = 0; i < 9; i++) tot += __shfl_sync(FULL, f, i);
        if (lane == 0) g_logZ[b] = logacc + __logf(tot);

        // ---------- gold path score (masked scan) + label copy ----------
        const int* lb = label + b * S;
        int t0 = lane * 16;

        int ll = -1;
#pragma unroll
        for (int k = 0; k < 16; k++) {
            int t = t0 + k;
            if ((t == 0) | (mb[t] > 0)) ll = t;
        }
        int inc = ll;
#pragma unroll
        for (int o = 1; o < 32; o <<= 1) {
            int vv = __shfl_up_sync(FULL, inc, o);
            if (lane >= o) inc = max(inc, vv);
        }
        int exc = __shfl_up_sync(FULL, inc, 1);
        if (lane == 0) exc = -1;
        int lastAll = __shfl_sync(FULL, inc, 31);

        float sc = 0.f;
        int prevIdx = exc;
#pragma unroll
        for (int k = 0; k < 16; k++) {
            int t = t0 + k;
            int mt = mb[t];
            int tg = lb[t];
            if (t >= 1) {
                int pt = lb[prevIdx];
                float s = trans[pt * 9 + tg] + emb[t * 9 + tg];
                sc += s * (float)mt;
            }
            if ((t == 0) | (mt > 0)) prevIdx = t;
        }
#pragma unroll
        for (int o = 16; o > 0; o >>= 1) sc += __shfl_xor_sync(FULL, sc, o);

        if (lane == 0) {
            int tg0 = lb[0];
            g_score[b] = startT[tg0] + emb[tg0] + sc + endT[lb[lastAll]];
        }

        float* lout = out + 2 + (long)B * S;
        for (int t = lane; t < S; t += 32)
            lout[(long)b * S + t] = (float)lb[t];

        __syncthreads();   // barrier #2
    }

    // ---------- per-block done accounting (warp0 only); last finalizes ----------
    __threadfence();
    unsigned my = 0;
    if (lane == 0) my = atomicAdd(&g_done, 1u);
    my = __shfl_sync(FULL, my, 0);
    if (my == 127u) {
        float d = 0.f, c = 0.f;
#pragma unroll
        for (int k = lane; k < 64; k += 32) {
            d += __ldcg(&g_score[k]) - __ldcg(&g_logZ[k]);
            c += __ldcg(&g_corr[k]);
        }
#pragma unroll
        for (int o = 16; o > 0; o >>= 1) {
            d += __shfl_xor_sync(FULL, d, o);
            c += __shfl_xor_sync(FULL, c, o);
        }
        if (lane == 0) {
            out[0] = -d / (float)B;
            out[1] = c;
            g_done = 0;   // reset for next graph replay
        }
    }
}

// ---------------------------------------------------------------------------
extern "C" void kernel_launch(void* const* d_in, const int* in_sizes, int n_in,
                              void* d_out, int out_size) {
    const float* hidden = (const float*)d_in[0];
    const int*   label  = (const int*)d_in[1];
    const int*   mask   = (const int*)d_in[2];
    const float* W      = (const float*)d_in[3];
    const float* bias   = (const float*)d_in[4];
    const float* startT = (const float*)d_in[5];
    const float* endT   = (const float*)d_in[6];
    const float* trans  = (const float*)d_in[7];
    float* out = (float*)d_out;

    emis_kernel<<<1024, 256>>>(hidden, W, bias);
    crf_kernel<<<128, 64>>>(label, mask, startT, endT, trans, out);
}

// round 12
// speedup vs baseline: 1.4448x; 1.0582x over previous
#include <cuda_runtime.h>
#include <cuda_bf16.h>

#define FULL 0xffffffffu

static constexpr int B = 64;
static constexpr int S = 512;
static constexpr int H = 768;
static constexpr int L = 9;
static constexpr int VROW = 12;   // floats per vbuf row (16B-aligned float4 reads)

__device__ float g_em[B * S * L];     // [b][t][j]
__device__ float g_score[B];
__device__ float g_logZ[B];
__device__ float g_corr[B];
__device__ unsigned g_done;           // finished crf blocks (target 128)

// ---------------------------------------------------------------------------
// Kernel 1: emissions = hidden @ W + b   (unchanged from round 11)
// ---------------------------------------------------------------------------
__global__ void __launch_bounds__(256) emis_kernel(const float* __restrict__ hidden,
                                                   const float* __restrict__ W,
                                                   const float* __restrict__ bias) {
    __shared__ float sWT[L * H];  // [j][h], 27648 B
    for (int i = threadIdx.x; i < L * H; i += 256) {
        int j = i / H, h = i - j * H;
        sWT[i] = W[h * L + j];
    }
    __syncthreads();

    int warp = threadIdx.x >> 5;
    int lane = threadIdx.x & 31;
    long row0 = (long)(blockIdx.x * 8 + warp) * 4;
    const float* h0 = hidden + row0 * H;

    float acc[4][9];
#pragma unroll
    for (int r = 0; r < 4; r++)
#pragma unroll
        for (int j = 0; j < 9; j++) acc[r][j] = 0.f;

#pragma unroll
    for (int k = 0; k < 6; k++) {
        int hb = k * 128 + lane * 4;
        float4 x0 = *(const float4*)(h0 + hb);
        float4 x1 = *(const float4*)(h0 + H + hb);
        float4 x2 = *(const float4*)(h0 + 2 * H + hb);
        float4 x3 = *(const float4*)(h0 + 3 * H + hb);
#pragma unroll
        for (int j = 0; j < 9; j++) {
            float4 w4 = *(const float4*)(sWT + j * H + hb);
            acc[0][j] = fmaf(x0.x, w4.x, acc[0][j]);
            acc[0][j] = fmaf(x0.y, w4.y, acc[0][j]);
            acc[0][j] = fmaf(x0.z, w4.z, acc[0][j]);
            acc[0][j] = fmaf(x0.w, w4.w, acc[0][j]);
            acc[1][j] = fmaf(x1.x, w4.x, acc[1][j]);
            acc[1][j] = fmaf(x1.y, w4.y, acc[1][j]);
            acc[1][j] = fmaf(x1.z, w4.z, acc[1][j]);
            acc[1][j] = fmaf(x1.w, w4.w, acc[1][j]);
            acc[2][j] = fmaf(x2.x, w4.x, acc[2][j]);
            acc[2][j] = fmaf(x2.y, w4.y, acc[2][j]);
            acc[2][j] = fmaf(x2.z, w4.z, acc[2][j]);
            acc[2][j] = fmaf(x2.w, w4.w, acc[2][j]);
            acc[3][j] = fmaf(x3.x, w4.x, acc[3][j]);
            acc[3][j] = fmaf(x3.y, w4.y, acc[3][j]);
            acc[3][j] = fmaf(x3.z, w4.z, acc[3][j]);
            acc[3][j] = fmaf(x3.w, w4.w, acc[3][j]);
        }
    }

#pragma unroll
    for (int r = 0; r < 4; r++)
#pragma unroll
        for (int j = 0; j < 9; j++) {
#pragma unroll
            for (int o = 16; o > 0; o >>= 1)
                acc[r][j] += __shfl_xor_sync(FULL, acc[r][j], o);
        }

    if (lane == 0) {
        float v[36];
#pragma unroll
        for (int r = 0; r < 4; r++)
#pragma unroll
            for (int j = 0; j < 9; j++) v[r * 9 + j] = acc[r][j] + bias[j];
        float4* dst = (float4*)(g_em + row0 * 9);  // row0 mult of 4 -> 144B aligned
#pragma unroll
        for (int q = 0; q < 9; q++)
            dst[q] = make_float4(v[4 * q], v[4 * q + 1], v[4 * q + 2], v[4 * q + 3]);
    }
}

// ---------------------------------------------------------------------------
// Kernel 2: 128 blocks x 64 threads.
//   blocks   0.. 63 : warp0 = slim Viterbi value chain (shfl transport,
//                     trajectory store off-chain); warp1 = trailing bp pass;
//                     then warp0 backtrace + predict + correct.
//   blocks  64..127 : warp0 = forward DP (shfl transport) + numerator +
//                     label copy; warp1 idles.
// Last finishing block finalizes loss/correct and resets g_done.
// ---------------------------------------------------------------------------
__global__ void __launch_bounds__(64)
crf_kernel(const int* __restrict__ label,
           const int* __restrict__ mask,
           const float* __restrict__ startT,
           const float* __restrict__ endT,
           const float* __restrict__ trans,
           float* __restrict__ out) {
    __shared__ __align__(16) float vbuf[(S - 1) * VROW]; // v(t-1) rows, 24528 B
    __shared__ unsigned char bp[(S - 1) * L];            // backpointers
    __shared__ unsigned char comp[255 * L];              // 2-step composed ptrs
    __shared__ unsigned char etag[256];                  // tags at even t
    __shared__ int prog;                                 // forward progress (t)

    int blk = blockIdx.x;
    int tid = threadIdx.x;
    int warp = tid >> 5;
    int lane = tid & 31;
    int jj = lane % 9;

    if (tid == 0) prog = 0;
    __syncthreads();   // barrier #1 (all threads, both block kinds)

    if (blk < 64) {
        int b = blk;
        const float* emb = g_em + (long)b * S * L;

        if (warp == 0) {
            // ===== Viterbi value chain: shfl transport, minimal step =====
            float Tc[9];
#pragma unroll
            for (int i = 0; i < 9; i++) Tc[i] = trans[i * 9 + jj];
            float v = startT[jj] + emb[jj];

            float cur[8];
#pragma unroll
            for (int k = 0; k < 8; k++) cur[k] = emb[(1 + k) * 9 + jj];

            int tb = 1;
            for (; tb + 8 <= S; tb += 8) {
                float nxt[8];
#pragma unroll
                for (int k = 0; k < 8; k++) {
                    int t2 = tb + 8 + k;
                    nxt[k] = (t2 < S) ? emb[t2 * 9 + jj] : 0.f;
                }
#pragma unroll
                for (int k = 0; k < 8; k++) {
                    int t = tb + k;
                    float e = cur[k];
                    if (lane < 9) vbuf[(t - 1) * VROW + jj] = v;  // off-chain store
                    float u0 = __shfl_sync(FULL, v, 0) + Tc[0];
                    float u1 = __shfl_sync(FULL, v, 1) + Tc[1];
                    float u2 = __shfl_sync(FULL, v, 2) + Tc[2];
                    float u3 = __shfl_sync(FULL, v, 3) + Tc[3];
                    float u4 = __shfl_sync(FULL, v, 4) + Tc[4];
                    float u5 = __shfl_sync(FULL, v, 5) + Tc[5];
                    float u6 = __shfl_sync(FULL, v, 6) + Tc[6];
                    float u7 = __shfl_sync(FULL, v, 7) + Tc[7];
                    float u8 = __shfl_sync(FULL, v, 8) + Tc[8];
                    float b01 = fmaxf(u0, u1);
                    float b23 = fmaxf(u2, u3);
                    float b45 = fmaxf(u4, u5);
                    float b67 = fmaxf(u6, u7);
                    float U = fmaxf(fmaxf(fmaxf(b01, b23), fmaxf(b45, b67)), u8);
                    v = U + e;   // == max_i((v_i+T_ij)+e) by rounding monotonicity
                }
#pragma unroll
                for (int k = 0; k < 8; k++) cur[k] = nxt[k];
                __syncwarp();
                if (lane == 0) { __threadfence_block(); *(volatile int*)&prog = tb + 7; }
            }
#pragma unroll
            for (int k = 0; k < 7; k++) {                 // t = 505..511
                int t = tb + k;
                float e = cur[k];
                if (lane < 9) vbuf[(t - 1) * VROW + jj] = v;
                float u0 = __shfl_sync(FULL, v, 0) + Tc[0];
                float u1 = __shfl_sync(FULL, v, 1) + Tc[1];
                float u2 = __shfl_sync(FULL, v, 2) + Tc[2];
                float u3 = __shfl_sync(FULL, v, 3) + Tc[3];
                float u4 = __shfl_sync(FULL, v, 4) + Tc[4];
                float u5 = __shfl_sync(FULL, v, 5) + Tc[5];
                float u6 = __shfl_sync(FULL, v, 6) + Tc[6];
                float u7 = __shfl_sync(FULL, v, 7) + Tc[7];
                float u8 = __shfl_sync(FULL, v, 8) + Tc[8];
                float b01 = fmaxf(u0, u1);
                float b23 = fmaxf(u2, u3);
                float b45 = fmaxf(u4, u5);
                float b67 = fmaxf(u6, u7);
                float U = fmaxf(fmaxf(fmaxf(b01, b23), fmaxf(b45, b67)), u8);
                v = U + e;
            }
            __syncwarp();
            if (lane == 0) { __threadfence_block(); *(volatile int*)&prog = S - 1; }
            __syncwarp();

            // final tag (all lanes compute identically)
            float fj = v + endT[jj];
            float fv[9];
#pragma unroll
            for (int i = 0; i < 9; i++) fv[i] = __shfl_sync(FULL, fj, i);
            float best = fv[0];
            int tag511 = 0;
#pragma unroll
            for (int i = 1; i < 9; i++)
                if (fv[i] > best) { best = fv[i]; tag511 = i; }   // first-max tie

            __syncthreads();   // barrier #2: join warp1's bp table

            // build 2-step composed pointers, even t in [2,510]
            for (int idx = lane; idx < 255 * 9; idx += 32) {
                int ci = idx / 9;
                int j = idx - ci * 9;
                int t = 2 * ci + 2;
                comp[idx] = bp[(t - 2) * 9 + bp[(t - 1) * 9 + j]];
            }
            __syncwarp();

            if (lane == 0) {
                int cur_t = bp[510 * 9 + tag511];   // tag at t=510
                etag[255] = (unsigned char)cur_t;
                for (int t = 510; t >= 2; t -= 2) {
                    cur_t = comp[((t - 2) >> 1) * 9 + cur_t];
                    etag[(t - 2) >> 1] = (unsigned char)cur_t;
                }
            }
            __syncwarp();

            const int* lb = label + b * S;
            float* pout = out + 2 + (long)b * S;
            float cnt = 0.f;
            for (int t = lane; t < S; t += 32) {
                int tg;
                if (t == 511) tg = tag511;
                else if ((t & 1) == 0) tg = etag[t >> 1];
                else tg = bp[t * 9 + etag[(t + 1) >> 1]];
                int lab = lb[t];
                int pv = (lab > 0) ? tg : 0;
                pout[t] = (float)pv;
                cnt += (pv == lab) ? 1.f : 0.f;
            }
#pragma unroll
            for (int o = 16; o > 0; o >>= 1) cnt += __shfl_xor_sync(FULL, cnt, o);
            if (lane == 0) g_corr[b] = cnt;

        } else {
            // ===== trailing bp/argmax pass (bit-identical to inline form) =====
            float Tc[9];
#pragma unroll
            for (int i = 0; i < 9; i++) Tc[i] = trans[i * 9 + jj];
            int g = lane / 9;                 // group 0..2 (lanes 27..31 idle)
            bool act = (lane < 27);

            for (int tc = 1; tc <= S - 1; tc += 3) {
                int t = tc + g;
                int need = tc + 2 < S - 1 ? tc + 2 : S - 1;
                while (*(volatile int*)&prog < need) __nanosleep(64);
                if (act && t <= S - 1) {
                    const float* vb = &vbuf[(t - 1) * VROW];
                    float4 a0 = *(const float4*)(vb);
                    float4 a1 = *(const float4*)(vb + 4);
                    float v8 = vb[8];
                    float e = emb[t * 9 + jj];
                    float vi[9];
                    vi[0] = (a0.x + Tc[0]) + e;   // ref op order
                    vi[1] = (a0.y + Tc[1]) + e;
                    vi[2] = (a0.z + Tc[2]) + e;
                    vi[3] = (a0.w + Tc[3]) + e;
                    vi[4] = (a1.x + Tc[4]) + e;
                    vi[5] = (a1.y + Tc[5]) + e;
                    vi[6] = (a1.z + Tc[6]) + e;
                    vi[7] = (a1.w + Tc[7]) + e;
                    vi[8] = (v8 + Tc[8]) + e;
                    float a01 = fmaxf(vi[0], vi[1]);
                    float a23 = fmaxf(vi[2], vi[3]);
                    float a45 = fmaxf(vi[4], vi[5]);
                    float a67 = fmaxf(vi[6], vi[7]);
                    float M = fmaxf(fmaxf(fmaxf(a01, a23), fmaxf(a45, a67)), vi[8]);
                    int arg = 8;                  // first-occurrence
#pragma unroll
                    for (int i = 7; i >= 0; i--) arg = (vi[i] == M) ? i : arg;
                    bp[(t - 1) * 9 + jj] = (unsigned char)arg;
                }
            }
            __syncthreads();   // barrier #2
            return;            // bp consumed by warp0 after the barrier
        }

    } else {
        if (warp == 1) { __syncthreads(); return; }   // barrier #2
        // ---------- forward DP (logZ), shfl transport, then numerator ----------
        int b = blk - 64;
        const float* emb = g_em + (long)b * S * L;
        const int* mb = mask + b * S;
        float E[9];
#pragma unroll
        for (int i = 0; i < 9; i++) E[i] = __expf(trans[i * 9 + jj]);
        float eend = __expf(endT[jj]);

        float p = __expf(startT[jj] + emb[jj]);
        float logacc = 0.f;

        float cur[8]; int mcur[8];
#pragma unroll
        for (int k = 0; k < 8; k++) { cur[k] = emb[(1 + k) * 9 + jj]; mcur[k] = mb[1 + k]; }

        int tb = 1;
        for (; tb + 8 <= S; tb += 8) {
            float w[8];
#pragma unroll
            for (int k = 0; k < 8; k++) w[k] = __expf(cur[k]);
            float nxt[8]; int mnxt[8];
#pragma unroll
            for (int k = 0; k < 8; k++) {
                int t2 = tb + 8 + k;
                if (t2 < S) { nxt[k] = emb[t2 * 9 + jj]; mnxt[k] = mb[t2]; }
                else        { nxt[k] = 0.f;              mnxt[k] = 0; }
            }
#pragma unroll
            for (int k = 0; k < 8; k++) {
                int t = tb + k;
                float p0 = __shfl_sync(FULL, p, 0), p1 = __shfl_sync(FULL, p, 1);
                float p2 = __shfl_sync(FULL, p, 2), p3 = __shfl_sync(FULL, p, 3);
                float p4 = __shfl_sync(FULL, p, 4), p5 = __shfl_sync(FULL, p, 5);
                float p6 = __shfl_sync(FULL, p, 6), p7 = __shfl_sync(FULL, p, 7);
                float p8 = __shfl_sync(FULL, p, 8);
                float s01 = fmaf(p0, E[0], p1 * E[1]);
                float s23 = fmaf(p2, E[2], p3 * E[3]);
                float s45 = fmaf(p4, E[4], p5 * E[5]);
                float s67 = fmaf(p6, E[6], p7 * E[7]);
                float s = ((s01 + s23) + (s45 + s67)) + p8 * E[8];
                float pn = s * w[k];
                p = (mcur[k] > 0) ? pn : p;
                if ((t & 15) == 0) {
                    float r = __shfl_sync(FULL, p, 0);
                    logacc += __logf(r);
                    p *= __fdividef(1.0f, r);
                }
            }
#pragma unroll
            for (int k = 0; k < 8; k++) { cur[k] = nxt[k]; mcur[k] = mnxt[k]; }
        }
#pragma unroll
        for (int k = 0; k < 7; k++) {     // t = 505..511
            float w = __expf(cur[k]);
            float p0 = __shfl_sync(FULL, p, 0), p1 = __shfl_sync(FULL, p, 1);
            float p2 = __shfl_sync(FULL, p, 2), p3 = __shfl_sync(FULL, p, 3);
            float p4 = __shfl_sync(FULL, p, 4), p5 = __shfl_sync(FULL, p, 5);
            float p6 = __shfl_sync(FULL, p, 6), p7 = __shfl_sync(FULL, p, 7);
            float p8 = __shfl_sync(FULL, p, 8);
            float s01 = fmaf(p0, E[0], p1 * E[1]);
            float s23 = fmaf(p2, E[2], p3 * E[3]);
            float s45 = fmaf(p4, E[4], p5 * E[5]);
            float s67 = fmaf(p6, E[6], p7 * E[7]);
            float s = ((s01 + s23) + (s45 + s67)) + p8 * E[8];
            float pn = s * w;
            p = (mcur[k] > 0) ? pn : p;
        }

        float f = p * eend;
        float tot = 0.f;
#pragma unroll
        for (int i = 0; i < 9; i++) tot += __shfl_sync(FULL, f, i);
        if (lane == 0) g_logZ[b] = logacc + __logf(tot);

        // ---------- gold path score (masked scan) + label copy ----------
        const int* lb = label + b * S;
        int t0 = lane * 16;

        int ll = -1;
#pragma unroll
        for (int k = 0; k < 16; k++) {
            int t = t0 + k;
            if ((t == 0) | (mb[t] > 0)) ll = t;
        }
        int inc = ll;
#pragma unroll
        for (int o = 1; o < 32; o <<= 1) {
            int vv = __shfl_up_sync(FULL, inc, o);
            if (lane >= o) inc = max(inc, vv);
        }
        int exc = __shfl_up_sync(FULL, inc, 1);
        if (lane == 0) exc = -1;
        int lastAll = __shfl_sync(FULL, inc, 31);

        float sc = 0.f;
        int prevIdx = exc;
#pragma unroll
        for (int k = 0; k < 16; k++) {
            int t = t0 + k;
            int mt = mb[t];
            int tg = lb[t];
            if (t >= 1) {
                int pt = lb[prevIdx];
                float s = trans[pt * 9 + tg] + emb[t * 9 + tg];
                sc += s * (float)mt;
            }
            if ((t == 0) | (mt > 0)) prevIdx = t;
        }
#pragma unroll
        for (int o = 16; o > 0; o >>= 1) sc += __shfl_xor_sync(FULL, sc, o);

        if (lane == 0) {
            int tg0 = lb[0];
            g_score[b] = startT[tg0] + emb[tg0] + sc + endT[lb[lastAll]];
        }

        float* lout = out + 2 + (long)B * S;
        for (int t = lane; t < S; t += 32)
            lout[(long)b * S + t] = (float)lb[t];

        __syncthreads();   // barrier #2
    }

    // ---------- per-block done accounting (warp0 only); last finalizes ----------
    __threadfence();
    unsigned my = 0;
    if (lane == 0) my = atomicAdd(&g_done, 1u);
    my = __shfl_sync(FULL, my, 0);
    if (my == 127u) {
        float d = 0.f, c = 0.f;
#pragma unroll
        for (int k = lane; k < 64; k += 32) {
            d += __ldcg(&g_score[k]) - __ldcg(&g_logZ[k]);
            c += __ldcg(&g_corr[k]);
        }
#pragma unroll
        for (int o = 16; o > 0; o >>= 1) {
            d += __shfl_xor_sync(FULL, d, o);
            c += __shfl_xor_sync(FULL, c, o);
        }
        if (lane == 0) {
            out[0] = -d / (float)B;
            out[1] = c;
            g_done = 0;   // reset for next graph replay
        }
    }
}

// ---------------------------------------------------------------------------
extern "C" void kernel_launch(void* const* d_in, const int* in_sizes, int n_in,
                              void* d_out, int out_size) {
    const float* hidden = (const float*)d_in[0];
    const int*   label  = (const int*)d_in[1];
    const int*   mask   = (const int*)d_in[2];
    const float* W      = (const float*)d_in[3];
    const float* bias   = (const float*)d_in[4];
    const float* startT = (const float*)d_in[5];
    const float* endT   = (const float*)d_in[6];
    const float* trans  = (const float*)d_in[7];
    float* out = (float*)d_out;

    emis_kernel<<<1024, 256>>>(hidden, W, bias);
    crf_kernel<<<128, 64>>>(label, mask, startT, endT, trans, out);
}

// round 13
// speedup vs baseline: 1.4461x; 1.0009x over previous
#include <cuda_runtime.h>
#include <cuda_bf16.h>

#define FULL 0xffffffffu

static constexpr int B = 64;
static constexpr int S = 512;
static constexpr int H = 768;
static constexpr int L = 9;
static constexpr int VROW = 12;   // floats per vbuf row (16B-aligned float4 reads)

__device__ float g_em[B * S * L];     // [b][t][j]
__device__ float g_score[B];
__device__ float g_logZ[B];
__device__ float g_corr[B];
__device__ unsigned g_done;           // finished crf blocks (target 128)

// ---------------------------------------------------------------------------
// Kernel 1: emissions = hidden @ W + b   (unchanged from round 12)
// ---------------------------------------------------------------------------
__global__ void __launch_bounds__(256) emis_kernel(const float* __restrict__ hidden,
                                                   const float* __restrict__ W,
                                                   const float* __restrict__ bias) {
    __shared__ float sWT[L * H];  // [j][h], 27648 B
    for (int i = threadIdx.x; i < L * H; i += 256) {
        int j = i / H, h = i - j * H;
        sWT[i] = W[h * L + j];
    }
    __syncthreads();

    int warp = threadIdx.x >> 5;
    int lane = threadIdx.x & 31;
    long row0 = (long)(blockIdx.x * 8 + warp) * 4;
    const float* h0 = hidden + row0 * H;

    float acc[4][9];
#pragma unroll
    for (int r = 0; r < 4; r++)
#pragma unroll
        for (int j = 0; j < 9; j++) acc[r][j] = 0.f;

#pragma unroll
    for (int k = 0; k < 6; k++) {
        int hb = k * 128 + lane * 4;
        float4 x0 = *(const float4*)(h0 + hb);
        float4 x1 = *(const float4*)(h0 + H + hb);
        float4 x2 = *(const float4*)(h0 + 2 * H + hb);
        float4 x3 = *(const float4*)(h0 + 3 * H + hb);
#pragma unroll
        for (int j = 0; j < 9; j++) {
            float4 w4 = *(const float4*)(sWT + j * H + hb);
            acc[0][j] = fmaf(x0.x, w4.x, acc[0][j]);
            acc[0][j] = fmaf(x0.y, w4.y, acc[0][j]);
            acc[0][j] = fmaf(x0.z, w4.z, acc[0][j]);
            acc[0][j] = fmaf(x0.w, w4.w, acc[0][j]);
            acc[1][j] = fmaf(x1.x, w4.x, acc[1][j]);
            acc[1][j] = fmaf(x1.y, w4.y, acc[1][j]);
            acc[1][j] = fmaf(x1.z, w4.z, acc[1][j]);
            acc[1][j] = fmaf(x1.w, w4.w, acc[1][j]);
            acc[2][j] = fmaf(x2.x, w4.x, acc[2][j]);
            acc[2][j] = fmaf(x2.y, w4.y, acc[2][j]);
            acc[2][j] = fmaf(x2.z, w4.z, acc[2][j]);
            acc[2][j] = fmaf(x2.w, w4.w, acc[2][j]);
            acc[3][j] = fmaf(x3.x, w4.x, acc[3][j]);
            acc[3][j] = fmaf(x3.y, w4.y, acc[3][j]);
            acc[3][j] = fmaf(x3.z, w4.z, acc[3][j]);
            acc[3][j] = fmaf(x3.w, w4.w, acc[3][j]);
        }
    }

#pragma unroll
    for (int r = 0; r < 4; r++)
#pragma unroll
        for (int j = 0; j < 9; j++) {
#pragma unroll
            for (int o = 16; o > 0; o >>= 1)
                acc[r][j] += __shfl_xor_sync(FULL, acc[r][j], o);
        }

    if (lane == 0) {
        float v[36];
#pragma unroll
        for (int r = 0; r < 4; r++)
#pragma unroll
            for (int j = 0; j < 9; j++) v[r * 9 + j] = acc[r][j] + bias[j];
        float4* dst = (float4*)(g_em + row0 * 9);  // row0 mult of 4 -> 144B aligned
#pragma unroll
        for (int q = 0; q < 9; q++)
            dst[q] = make_float4(v[4 * q], v[4 * q + 1], v[4 * q + 2], v[4 * q + 3]);
    }
}

// ---------------------------------------------------------------------------
// Kernel 2: 128 blocks x 64 threads.
// Chain warps use a 3-way i-split: lane (j = lane%9, g = (lane/9)%3).
// Per step: 3 gather shfls (per-lane src) + partial + 2 reduce shfls.
//   blocks   0.. 63 : warp0 = Viterbi value chain; warp1 = trailing bp pass;
//                     then warp0 backtrace + predict + correct.
//   blocks  64..127 : warp0 = forward DP + numerator + label copy; warp1 idles.
// ---------------------------------------------------------------------------
__global__ void __launch_bounds__(64)
crf_kernel(const int* __restrict__ label,
           const int* __restrict__ mask,
           const float* __restrict__ startT,
           const float* __restrict__ endT,
           const float* __restrict__ trans,
           float* __restrict__ out) {
    __shared__ __align__(16) float vbuf[(S - 1) * VROW]; // v(t-1) rows, 24528 B
    __shared__ unsigned char bp[(S - 1) * L];            // backpointers
    __shared__ unsigned char comp[255 * L];              // 2-step composed ptrs
    __shared__ unsigned char etag[256];                  // tags at even t
    __shared__ int prog;                                 // forward progress (t)

    int blk = blockIdx.x;
    int tid = threadIdx.x;
    int warp = tid >> 5;
    int lane = tid & 31;
    int jj = lane % 9;
    int gg = (lane / 9) % 3;          // lanes 27..31 mirror group 0
    int g3 = gg * 3;                  // base i for this lane's partial
    int peer1 = jj + 9 * ((gg + 1) % 3);
    int peer2 = jj + 9 * ((gg + 2) % 3);

    if (tid == 0) prog = 0;
    __syncthreads();   // barrier #1 (all threads, both block kinds)

    if (blk < 64) {
        int b = blk;
        const float* emb = g_em + (long)b * S * L;

        if (warp == 0) {
            // ===== Viterbi value chain: 3-way split, 5 shfls/step =====
            float T0 = trans[(g3 + 0) * 9 + jj];
            float T1 = trans[(g3 + 1) * 9 + jj];
            float T2 = trans[(g3 + 2) * 9 + jj];
            float v = startT[jj] + emb[jj];

            float cur[8];
#pragma unroll
            for (int k = 0; k < 8; k++) cur[k] = emb[(1 + k) * 9 + jj];

            int tb = 1;
            for (; tb + 8 <= S; tb += 8) {
                float nxt[8];
#pragma unroll
                for (int k = 0; k < 8; k++) {
                    int t2 = tb + 8 + k;
                    nxt[k] = (t2 < S) ? emb[t2 * 9 + jj] : 0.f;
                }
#pragma unroll
                for (int k = 0; k < 8; k++) {
                    int t = tb + k;
                    float e = cur[k];
                    if (lane < 9) vbuf[(t - 1) * VROW + jj] = v;  // off-chain store
                    float r0 = __shfl_sync(FULL, v, g3);
                    float r1 = __shfl_sync(FULL, v, g3 + 1);
                    float r2 = __shfl_sync(FULL, v, g3 + 2);
                    float u0 = r0 + T0;
                    float u1 = r1 + T1;
                    float u2 = r2 + T2;
                    float pm = fmaxf(fmaxf(u0, u1), u2);
                    float q1 = __shfl_sync(FULL, pm, peer1);
                    float q2 = __shfl_sync(FULL, pm, peer2);
                    float U = fmaxf(pm, fmaxf(q1, q2));  // max exact in any order
                    v = U + e;   // == max_i((v_i+T_ij)+e) by rounding monotonicity
                }
#pragma unroll
                for (int k = 0; k < 8; k++) cur[k] = nxt[k];
                __syncwarp();
                if (lane == 0) { __threadfence_block(); *(volatile int*)&prog = tb + 7; }
            }
#pragma unroll
            for (int k = 0; k < 7; k++) {                 // t = 505..511
                int t = tb + k;
                float e = cur[k];
                if (lane < 9) vbuf[(t - 1) * VROW + jj] = v;
                float r0 = __shfl_sync(FULL, v, g3);
                float r1 = __shfl_sync(FULL, v, g3 + 1);
                float r2 = __shfl_sync(FULL, v, g3 + 2);
                float u0 = r0 + T0;
                float u1 = r1 + T1;
                float u2 = r2 + T2;
                float pm = fmaxf(fmaxf(u0, u1), u2);
                float q1 = __shfl_sync(FULL, pm, peer1);
                float q2 = __shfl_sync(FULL, pm, peer2);
                float U = fmaxf(pm, fmaxf(q1, q2));
                v = U + e;
            }
            __syncwarp();
            if (lane == 0) { __threadfence_block(); *(volatile int*)&prog = S - 1; }
            __syncwarp();

            // final tag (v_j valid in lanes 0..8)
            float fj = v + endT[jj];
            float fv[9];
#pragma unroll
            for (int i = 0; i < 9; i++) fv[i] = __shfl_sync(FULL, fj, i);
            float best = fv[0];
            int tag511 = 0;
#pragma unroll
            for (int i = 1; i < 9; i++)
                if (fv[i] > best) { best = fv[i]; tag511 = i; }   // first-max tie

            __syncthreads();   // barrier #2: join warp1's bp table

            // build 2-step composed pointers, even t in [2,510]
            for (int idx = lane; idx < 255 * 9; idx += 32) {
                int ci = idx / 9;
                int j = idx - ci * 9;
                int t = 2 * ci + 2;
                comp[idx] = bp[(t - 2) * 9 + bp[(t - 1) * 9 + j]];
            }
            __syncwarp();

            if (lane == 0) {
                int cur_t = bp[510 * 9 + tag511];   // tag at t=510
                etag[255] = (unsigned char)cur_t;
                for (int t = 510; t >= 2; t -= 2) {
                    cur_t = comp[((t - 2) >> 1) * 9 + cur_t];
                    etag[(t - 2) >> 1] = (unsigned char)cur_t;
                }
            }
            __syncwarp();

            const int* lb = label + b * S;
            float* pout = out + 2 + (long)b * S;
            float cnt = 0.f;
            for (int t = lane; t < S; t += 32) {
                int tg;
                if (t == 511) tg = tag511;
                else if ((t & 1) == 0) tg = etag[t >> 1];
                else tg = bp[t * 9 + etag[(t + 1) >> 1]];
                int lab = lb[t];
                int pv = (lab > 0) ? tg : 0;
                pout[t] = (float)pv;
                cnt += (pv == lab) ? 1.f : 0.f;
            }
#pragma unroll
            for (int o = 16; o > 0; o >>= 1) cnt += __shfl_xor_sync(FULL, cnt, o);
            if (lane == 0) g_corr[b] = cnt;

        } else {
            // ===== trailing bp/argmax pass (bit-identical to inline form) =====
            float Tc[9];
#pragma unroll
            for (int i = 0; i < 9; i++) Tc[i] = trans[i * 9 + jj];
            int g = lane / 9;                 // group 0..2 (lanes 27..31 idle)
            bool act = (lane < 27);

            for (int tc = 1; tc <= S - 1; tc += 3) {
                int t = tc + g;
                int need = tc + 2 < S - 1 ? tc + 2 : S - 1;
                while (*(volatile int*)&prog < need) __nanosleep(64);
                if (act && t <= S - 1) {
                    const float* vb = &vbuf[(t - 1) * VROW];
                    float4 a0 = *(const float4*)(vb);
                    float4 a1 = *(const float4*)(vb + 4);
                    float v8 = vb[8];
                    float e = emb[t * 9 + jj];
                    float vi[9];
                    vi[0] = (a0.x + Tc[0]) + e;   // ref op order
                    vi[1] = (a0.y + Tc[1]) + e;
                    vi[2] = (a0.z + Tc[2]) + e;
                    vi[3] = (a0.w + Tc[3]) + e;
                    vi[4] = (a1.x + Tc[4]) + e;
                    vi[5] = (a1.y + Tc[5]) + e;
                    vi[6] = (a1.z + Tc[6]) + e;
                    vi[7] = (a1.w + Tc[7]) + e;
                    vi[8] = (v8 + Tc[8]) + e;
                    float a01 = fmaxf(vi[0], vi[1]);
                    float a23 = fmaxf(vi[2], vi[3]);
                    float a45 = fmaxf(vi[4], vi[5]);
                    float a67 = fmaxf(vi[6], vi[7]);
                    float M = fmaxf(fmaxf(fmaxf(a01, a23), fmaxf(a45, a67)), vi[8]);
                    int arg = 8;                  // first-occurrence
#pragma unroll
                    for (int i = 7; i >= 0; i--) arg = (vi[i] == M) ? i : arg;
                    bp[(t - 1) * 9 + jj] = (unsigned char)arg;
                }
            }
            __syncthreads();   // barrier #2
            return;            // bp consumed by warp0 after the barrier
        }

    } else {
        if (warp == 1) { __syncthreads(); return; }   // barrier #2
        // ---------- forward DP (logZ), 3-way split, then numerator ----------
        int b = blk - 64;
        const float* emb = g_em + (long)b * S * L;
        const int* mb = mask + b * S;
        float E0 = __expf(trans[(g3 + 0) * 9 + jj]);
        float E1 = __expf(trans[(g3 + 1) * 9 + jj]);
        float E2 = __expf(trans[(g3 + 2) * 9 + jj]);
        float eend = __expf(endT[jj]);

        float p = __expf(startT[jj] + emb[jj]);
        float logacc = 0.f;

        float cur[8]; int mcur[8];
#pragma unroll
        for (int k = 0; k < 8; k++) { cur[k] = emb[(1 + k) * 9 + jj]; mcur[k] = mb[1 + k]; }

        int tb = 1;
        for (; tb + 8 <= S; tb += 8) {
            float w[8];
#pragma unroll
            for (int k = 0; k < 8; k++) w[k] = __expf(cur[k]);
            float nxt[8]; int mnxt[8];
#pragma unroll
            for (int k = 0; k < 8; k++) {
                int t2 = tb + 8 + k;
                if (t2 < S) { nxt[k] = emb[t2 * 9 + jj]; mnxt[k] = mb[t2]; }
                else        { nxt[k] = 0.f;              mnxt[k] = 0; }
            }
#pragma unroll
            for (int k = 0; k < 8; k++) {
                int t = tb + k;
                float r0 = __shfl_sync(FULL, p, g3);
                float r1 = __shfl_sync(FULL, p, g3 + 1);
                float r2 = __shfl_sync(FULL, p, g3 + 2);
                float sp = fmaf(r0, E0, r1 * E1);
                sp = fmaf(r2, E2, sp);
                float q1 = __shfl_sync(FULL, sp, peer1);
                float q2 = __shfl_sync(FULL, sp, peer2);
                float s = (sp + q1) + q2;
                float pn = s * w[k];
                p = (mcur[k] > 0) ? pn : p;
                if ((t & 15) == 0) {
                    float r = __shfl_sync(FULL, p, 0);
                    logacc += __logf(r);
                    p *= __fdividef(1.0f, r);
                }
            }
#pragma unroll
            for (int k = 0; k < 8; k++) { cur[k] = nxt[k]; mcur[k] = mnxt[k]; }
        }
#pragma unroll
        for (int k = 0; k < 7; k++) {     // t = 505..511
            float w = __expf(cur[k]);
            float r0 = __shfl_sync(FULL, p, g3);
            float r1 = __shfl_sync(FULL, p, g3 + 1);
            float r2 = __shfl_sync(FULL, p, g3 + 2);
            float sp = fmaf(r0, E0, r1 * E1);
            sp = fmaf(r2, E2, sp);
            float q1 = __shfl_sync(FULL, sp, peer1);
            float q2 = __shfl_sync(FULL, sp, peer2);
            float s = (sp + q1) + q2;
            float pn = s * w;
            p = (mcur[k] > 0) ? pn : p;
        }

        float f = p * eend;
        float tot = 0.f;
#pragma unroll
        for (int i = 0; i < 9; i++) tot += __shfl_sync(FULL, f, i);
        if (lane == 0) g_logZ[b] = logacc + __logf(tot);

        // ---------- gold path score (masked scan) + label copy ----------
        const int* lb = label + b * S;
        int t0 = lane * 16;

        int ll = -1;
#pragma unroll
        for (int k = 0; k < 16; k++) {
            int t = t0 + k;
            if ((t == 0) | (mb[t] > 0)) ll = t;
        }
        int inc = ll;
#pragma unroll
        for (int o = 1; o < 32; o <<= 1) {
            int vv = __shfl_up_sync(FULL, inc, o);
            if (lane >= o) inc = max(inc, vv);
        }
        int exc = __shfl_up_sync(FULL, inc, 1);
        if (lane == 0) exc = -1;
        int lastAll = __shfl_sync(FULL, inc, 31);

        float sc = 0.f;
        int prevIdx = exc;
#pragma unroll
        for (int k = 0; k < 16; k++) {
            int t = t0 + k;
            int mt = mb[t];
            int tg = lb[t];
            if (t >= 1) {
                int pt = lb[prevIdx];
                float s = trans[pt * 9 + tg] + emb[t * 9 + tg];
                sc += s * (float)mt;
            }
            if ((t == 0) | (mt > 0)) prevIdx = t;
        }
#pragma unroll
        for (int o = 16; o > 0; o >>= 1) sc += __shfl_xor_sync(FULL, sc, o);

        if (lane == 0) {
            int tg0 = lb[0];
            g_score[b] = startT[tg0] + emb[tg0] + sc + endT[lb[lastAll]];
        }

        float* lout = out + 2 + (long)B * S;
        for (int t = lane; t < S; t += 32)
            lout[(long)b * S + t] = (float)lb[t];

        __syncthreads();   // barrier #2
    }

    // ---------- per-block done accounting (warp0 only); last finalizes ----------
    __threadfence();
    unsigned my = 0;
    if (lane == 0) my = atomicAdd(&g_done, 1u);
    my = __shfl_sync(FULL, my, 0);
    if (my == 127u) {
        float d = 0.f, c = 0.f;
#pragma unroll
        for (int k = lane; k < 64; k += 32) {
            d += __ldcg(&g_score[k]) - __ldcg(&g_logZ[k]);
            c += __ldcg(&g_corr[k]);
        }
#pragma unroll
        for (int o = 16; o > 0; o >>= 1) {
            d += __shfl_xor_sync(FULL, d, o);
            c += __shfl_xor_sync(FULL, c, o);
        }
        if (lane == 0) {
            out[0] = -d / (float)B;
            out[1] = c;
            g_done = 0;   // reset for next graph replay
        }
    }
}

// ---------------------------------------------------------------------------
extern "C" void kernel_launch(void* const* d_in, const int* in_sizes, int n_in,
                              void* d_out, int out_size) {
    const float* hidden = (const float*)d_in[0];
    const int*   label  = (const int*)d_in[1];
    const int*   mask   = (const int*)d_in[2];
    const float* W      = (const float*)d_in[3];
    const float* bias   = (const float*)d_in[4];
    const float* startT = (const float*)d_in[5];
    const float* endT   = (const float*)d_in[6];
    const float* trans  = (const float*)d_in[7];
    float* out = (float*)d_out;

    emis_kernel<<<1024, 256>>>(hidden, W, bias);
    crf_kernel<<<128, 64>>>(label, mask, startT, endT, trans, out);
}